// round 14
// baseline (speedup 1.0000x reference)
#include <cuda_runtime.h>
#include <cuda_bf16.h>
#include <cstdint>
#include <math.h>

// Problem constants
#define B_   256
#define G_   20000
#define L_   512
#define GD_  256
#define H_   8
#define HD_  64
#define SCALE_ 0.125f
#define CTX_SPLITS 20
#define CTX_CHUNK  1024     // 20*1024 >= 20000; last chunk 544 (guarded)
#define NT_  313            // score n-tiles (ceil(20000/64))

// ------------------------- device scratch (static; no allocs) ---------------
__device__ float g_V[G_ * L_];
__device__ float g_ctxp[H_ * CTX_SPLITS * B_ * HD_];
__device__ float g_h[B_ * L_];
__device__ float g_pmax[B_ * H_ * NT_];
__device__ float g_psum[B_ * H_ * NT_];
__device__ float g_rmax[B_ * H_];
__device__ float g_rinv[B_ * H_];

__device__ __nv_bfloat16 g_zh[B_ * L_],  g_zl[B_ * L_];
__device__ __nv_bfloat16 g_geh[G_ * GD_], g_gel[G_ * GD_];
__device__ __nv_bfloat16 g_Wqh[L_ * L_],  g_Wql[L_ * L_];
__device__ __nv_bfloat16 g_Wkh[L_ * GD_], g_Wkl[L_ * GD_];
__device__ __nv_bfloat16 g_Wvh[L_ * GD_], g_Wvl[L_ * GD_];
__device__ __nv_bfloat16 g_W1h[L_ * L_],  g_W1l[L_ * L_];
__device__ __nv_bfloat16 g_W2h[G_ * L_],  g_W2l[G_ * L_];
__device__ __nv_bfloat16 g_Qh[B_ * L_],  g_Ql[B_ * L_];
__device__ __nv_bfloat16 g_Kh[G_ * L_],  g_Kl[G_ * L_];
__device__ __nv_bfloat16 g_cth[B_ * L_], g_ctl[B_ * L_];
__device__ __nv_bfloat16 g_hh[B_ * L_],  g_hl[B_ * L_];
__device__ __nv_bfloat16 g_ath[B_ * H_ * G_];                        // attn hi plane
__device__ __nv_bfloat16 g_Vth[L_ * G_], g_Vtl[L_ * G_];             // V^T planes

// ------------------------- helpers ------------------------------------------
__device__ __forceinline__ uint32_t smem_u32(const void* p) {
    uint32_t addr;
    asm("{ .reg .u64 tmp; cvta.to.shared.u64 tmp, %1; cvt.u32.u64 %0, tmp; }"
        : "=r"(addr) : "l"(p));
    return addr;
}

__device__ __forceinline__ void mma16816(float* c, const uint32_t* a, const uint32_t* b)
{
    asm volatile(
        "mma.sync.aligned.m16n8k16.row.col.f32.bf16.bf16.f32 "
        "{%0,%1,%2,%3}, {%4,%5,%6,%7}, {%8,%9}, {%0,%1,%2,%3};"
        : "+f"(c[0]), "+f"(c[1]), "+f"(c[2]), "+f"(c[3])
        : "r"(a[0]), "r"(a[1]), "r"(a[2]), "r"(a[3]), "r"(b[0]), "r"(b[1]));
}

__device__ __forceinline__ void ldsm4(uint32_t* r, uint32_t addr)
{
    asm volatile("ldmatrix.sync.aligned.m8n8.x4.shared.b16 {%0,%1,%2,%3}, [%4];"
                 : "=r"(r[0]), "=r"(r[1]), "=r"(r[2]), "=r"(r[3]) : "r"(addr));
}

__device__ __forceinline__ void cpa16(uint32_t dst, const void* src, int vld)
{
    asm volatile("cp.async.cg.shared.global [%0], [%1], 16, %2;"
                 :: "r"(dst), "l"(src), "r"(vld) : "memory");
}

__device__ __forceinline__ uint32_t pack_hi(float x, float y, float* rx, float* ry)
{
    __nv_bfloat16 hx = __float2bfloat16(x);
    __nv_bfloat16 hy = __float2bfloat16(y);
    *rx = x - __bfloat162float(hx);
    *ry = y - __bfloat162float(hy);
    __nv_bfloat162 p = {hx, hy};
    return *(uint32_t*)&p;
}
__device__ __forceinline__ uint32_t pack_bf2(float x, float y)
{
    __nv_bfloat162 p = {__float2bfloat16(x), __float2bfloat16(y)};
    return *(uint32_t*)&p;
}

// ------------------------- planar bf16x3 GEMM (validated core) ---------------
// Al == nullptr -> A-hi-only mode: skips Al loads and the lo*hi MMA block.
#define STAGE_BYTES 49152

__global__ __launch_bounds__(256, 2) void bf_gemm(
    const __nv_bfloat16* __restrict__ Ah, const __nv_bfloat16* __restrict__ Al,
    const __nv_bfloat16* __restrict__ Bh, const __nv_bfloat16* __restrict__ Bl,
    float* __restrict__ C, const float* __restrict__ bias,
    __nv_bfloat16* __restrict__ Ch, __nv_bfloat16* __restrict__ Cl,
    int M, int N, int K, int lda, int ldb, long ldc, int ldcp,
    long aZ, long bZ, long cZ, int kSplit, int kChunk, float alpha)
{
    extern __shared__ char smem[];
    const uint32_t smemBase = smem_u32(smem);

    const int tid = threadIdx.x;
    const int wid = tid >> 5, lane = tid & 31;
    const int wm = wid & 3, wn = wid >> 2;

    const int z = blockIdx.z;
    const int h = z / kSplit, sK = z % kSplit;
    Ah += (long)h * aZ;
    if (Al) Al += (long)h * aZ;
    Bh += (long)h * bZ; Bl += (long)h * bZ;
    if (C) C += (long)z * cZ;
    const int kStart = sK * kChunk;
    const int kEnd = min(K, kStart + kChunk);
    const int m0 = blockIdx.y * 128, n0 = blockIdx.x * 64;

    const uint32_t x7 = lane & 7;
    const uint32_t caB = (lane >> 4) & 1;
    const uint32_t cbB = (lane >> 3) & 1;
    const uint32_t aRowOff = (uint32_t)((lane & 7) + (lane & 8));
    const uint32_t bRowOff = (uint32_t)((lane & 7) + ((lane & 16) >> 1));
    uint32_t aR[2], bR[2];
#pragma unroll
    for (int mt = 0; mt < 2; mt++) aR[mt] = (uint32_t)(wm * 32 + mt * 16 + aRowOff) * 128u;
#pragma unroll
    for (int j = 0; j < 2; j++)  bR[j] = (uint32_t)(wn * 32 + j * 16 + bRowOff) * 128u;

    float acc[2][4][4];
#pragma unroll
    for (int i = 0; i < 2; i++)
#pragma unroll
        for (int j = 0; j < 4; j++)
#pragma unroll
            for (int r = 0; r < 4; r++) acc[i][j][r] = 0.f;

    const int KI = (kEnd - kStart + 63) >> 6;

    auto load_stage = [&](int it) {
        const int k0 = kStart + (it << 6);
        const uint32_t sb = smemBase + (uint32_t)(it & 1) * STAGE_BYTES;
#pragma unroll
        for (int i = 0; i < 4; i++) {
            int e = tid + (i << 8);
            int row = e >> 3, kc = e & 7;
            int gm = m0 + row, gk = k0 + (kc << 3);
            int v = (gm < M && gk + 8 <= kEnd) ? 16 : 0;
            long off = v ? ((long)gm * lda + gk) : 0;
            uint32_t dst = sb + (uint32_t)row * 128u + ((uint32_t)(kc ^ (row & 7)) << 4);
            cpa16(dst, Ah + off, v);
            if (Al) cpa16(dst + 16384, Al + off, v);
        }
#pragma unroll
        for (int i = 0; i < 2; i++) {
            int e = tid + (i << 8);
            int row = e >> 3, kc = e & 7;
            int gn = n0 + row, gk = k0 + (kc << 3);
            int v = (gn < N && gk + 8 <= kEnd) ? 16 : 0;
            long off = v ? ((long)gn * ldb + gk) : 0;
            uint32_t dst = sb + 32768u + (uint32_t)row * 128u + ((uint32_t)(kc ^ (row & 7)) << 4);
            cpa16(dst,        Bh + off, v);
            cpa16(dst + 8192, Bl + off, v);
        }
        asm volatile("cp.async.commit_group;" ::: "memory");
    };

    load_stage(0);

    for (int it = 0; it < KI; ++it) {
        asm volatile("cp.async.wait_group 0;" ::: "memory");
        __syncthreads();
        if (it + 1 < KI) load_stage(it + 1);

        const uint32_t sb = smemBase + (uint32_t)(it & 1) * STAGE_BYTES;
        uint32_t faH[2][4], faL[2][4], fb[2][4];
#pragma unroll
        for (int s = 0; s < 4; s++) {
            const uint32_t ac = (((uint32_t)(2 * s) + caB) ^ x7) << 4;
            const uint32_t bc = (((uint32_t)(2 * s) + cbB) ^ x7) << 4;
            ldsm4(faH[0], sb + aR[0] + ac);
            ldsm4(faH[1], sb + aR[1] + ac);
            ldsm4(fb[0],  sb + 32768u + bR[0] + bc);
            ldsm4(fb[1],  sb + 32768u + bR[1] + bc);
#pragma unroll
            for (int mt = 0; mt < 2; mt++)
#pragma unroll
                for (int nt = 0; nt < 4; nt++)
                    mma16816(acc[mt][nt], faH[mt], &fb[nt >> 1][(nt & 1) << 1]);
            if (Al) {
                ldsm4(faL[0], sb + 16384u + aR[0] + ac);
                ldsm4(faL[1], sb + 16384u + aR[1] + ac);
#pragma unroll
                for (int mt = 0; mt < 2; mt++)
#pragma unroll
                    for (int nt = 0; nt < 4; nt++)
                        mma16816(acc[mt][nt], faL[mt], &fb[nt >> 1][(nt & 1) << 1]);
            }
            ldsm4(fb[0], sb + 40960u + bR[0] + bc);
            ldsm4(fb[1], sb + 40960u + bR[1] + bc);
#pragma unroll
            for (int mt = 0; mt < 2; mt++)
#pragma unroll
                for (int nt = 0; nt < 4; nt++)
                    mma16816(acc[mt][nt], faH[mt], &fb[nt >> 1][(nt & 1) << 1]);
        }
        __syncthreads();
    }

    const int grp = lane >> 2, tig = lane & 3;
#pragma unroll
    for (int mt = 0; mt < 2; mt++) {
#pragma unroll
        for (int nt = 0; nt < 4; nt++) {
            int rm = m0 + (wm << 5) + (mt << 4) + grp;
            int cn = n0 + (wn << 5) + (nt << 3) + (tig << 1);
            if (cn >= N) continue;
            float bx = 0.f, by = 0.f;
            if (bias) { bx = bias[cn]; by = bias[cn + 1]; }
#pragma unroll
            for (int rr = 0; rr < 2; rr++) {
                int r = rm + rr * 8;
                if (r >= M) continue;
                float vx = acc[mt][nt][rr * 2 + 0] * alpha + bx;
                float vy = acc[mt][nt][rr * 2 + 1] * alpha + by;
                if (C) *(float2*)&C[(long)r * ldc + cn] = make_float2(vx, vy);
                if (Ch) {
                    float lx, ly;
                    uint32_t hw = pack_hi(vx, vy, &lx, &ly);
                    uint32_t lw = pack_bf2(lx, ly);
                    *(uint32_t*)&Ch[(long)r * ldcp + cn] = hw;
                    *(uint32_t*)&Cl[(long)r * ldcp + cn] = lw;
                }
            }
        }
    }
}

// ------------------------- head-looped scores GEMM + softmax partials --------
__global__ __launch_bounds__(256, 2) void scores_gemm(
    const __nv_bfloat16* __restrict__ Ah, const __nv_bfloat16* __restrict__ Al,
    const __nv_bfloat16* __restrict__ Bh, const __nv_bfloat16* __restrict__ Bl,
    float* __restrict__ C, float* __restrict__ pmax, float* __restrict__ psum)
{
    extern __shared__ char smem[];
    __shared__ float redbuf[512];
    const uint32_t smemBase = smem_u32(smem);

    const int tid = threadIdx.x;
    const int wid = tid >> 5, lane = tid & 31;
    const int wm = wid & 3, wn = wid >> 2;
    const int m0 = blockIdx.y * 128, n0 = blockIdx.x * 64;

    const uint32_t x7 = lane & 7;
    const uint32_t caB = (lane >> 4) & 1;
    const uint32_t cbB = (lane >> 3) & 1;
    const uint32_t aRowOff = (uint32_t)((lane & 7) + (lane & 8));
    const uint32_t bRowOff = (uint32_t)((lane & 7) + ((lane & 16) >> 1));
    uint32_t aR[2], bR[2];
#pragma unroll
    for (int mt = 0; mt < 2; mt++) aR[mt] = (uint32_t)(wm * 32 + mt * 16 + aRowOff) * 128u;
#pragma unroll
    for (int j = 0; j < 2; j++)  bR[j] = (uint32_t)(wn * 32 + j * 16 + bRowOff) * 128u;

    float acc[2][4][4];
#pragma unroll
    for (int i = 0; i < 2; i++)
#pragma unroll
        for (int j = 0; j < 4; j++)
#pragma unroll
            for (int r = 0; r < 4; r++) acc[i][j][r] = 0.f;

    auto load_stage = [&](int hh) {
        const int k0 = hh << 6;
        const uint32_t sb = smemBase + (uint32_t)(hh & 1) * STAGE_BYTES;
#pragma unroll
        for (int i = 0; i < 4; i++) {
            int e = tid + (i << 8);
            int row = e >> 3, kc = e & 7;
            long off = (long)(m0 + row) * L_ + k0 + (kc << 3);
            uint32_t dst = sb + (uint32_t)row * 128u + ((uint32_t)(kc ^ (row & 7)) << 4);
            cpa16(dst,         Ah + off, 16);
            cpa16(dst + 16384, Al + off, 16);
        }
#pragma unroll
        for (int i = 0; i < 2; i++) {
            int e = tid + (i << 8);
            int row = e >> 3, kc = e & 7;
            int gn = n0 + row;
            int v = (gn < G_) ? 16 : 0;
            long off = v ? ((long)gn * L_ + k0 + (kc << 3)) : 0;
            uint32_t dst = sb + 32768u + (uint32_t)row * 128u + ((uint32_t)(kc ^ (row & 7)) << 4);
            cpa16(dst,        Bh + off, v);
            cpa16(dst + 8192, Bl + off, v);
        }
        asm volatile("cp.async.commit_group;" ::: "memory");
    };

    load_stage(0);
    const int grp = lane >> 2, tig = lane & 3;

    for (int h = 0; h < H_; ++h) {
        asm volatile("cp.async.wait_group 0;" ::: "memory");
        __syncthreads();
        if (h + 1 < H_) load_stage(h + 1);

        const uint32_t sb = smemBase + (uint32_t)(h & 1) * STAGE_BYTES;
        uint32_t faH[2][4], faL[2][4], fb[2][4];
#pragma unroll
        for (int s = 0; s < 4; s++) {
            const uint32_t ac = (((uint32_t)(2 * s) + caB) ^ x7) << 4;
            const uint32_t bc = (((uint32_t)(2 * s) + cbB) ^ x7) << 4;
            ldsm4(faH[0], sb + aR[0] + ac);
            ldsm4(faH[1], sb + aR[1] + ac);
            ldsm4(faL[0], sb + 16384u + aR[0] + ac);
            ldsm4(faL[1], sb + 16384u + aR[1] + ac);
            ldsm4(fb[0],  sb + 32768u + bR[0] + bc);
            ldsm4(fb[1],  sb + 32768u + bR[1] + bc);
#pragma unroll
            for (int mt = 0; mt < 2; mt++)
#pragma unroll
                for (int nt = 0; nt < 4; nt++)
                    mma16816(acc[mt][nt], faH[mt], &fb[nt >> 1][(nt & 1) << 1]);
#pragma unroll
            for (int mt = 0; mt < 2; mt++)
#pragma unroll
                for (int nt = 0; nt < 4; nt++)
                    mma16816(acc[mt][nt], faL[mt], &fb[nt >> 1][(nt & 1) << 1]);
            ldsm4(fb[0], sb + 40960u + bR[0] + bc);
            ldsm4(fb[1], sb + 40960u + bR[1] + bc);
#pragma unroll
            for (int mt = 0; mt < 2; mt++)
#pragma unroll
                for (int nt = 0; nt < 4; nt++)
                    mma16816(acc[mt][nt], faH[mt], &fb[nt >> 1][(nt & 1) << 1]);
        }

        // ---- per-head epilogue: write raw scores + per-(row,tile) partials
        float* Cr = C + (long)h * G_;
#pragma unroll
        for (int mt = 0; mt < 2; mt++) {
#pragma unroll
            for (int rr = 0; rr < 2; rr++) {
                int r = m0 + (wm << 5) + (mt << 4) + grp + (rr << 3);
                float vals[8];
                float mx = -1e30f;
#pragma unroll
                for (int nt = 0; nt < 4; nt++) {
                    int cn = n0 + (wn << 5) + (nt << 3) + (tig << 1);
                    float vx = acc[mt][nt][rr * 2 + 0] * SCALE_;
                    float vy = acc[mt][nt][rr * 2 + 1] * SCALE_;
                    bool ok = (cn < G_);
                    if (ok) *(float2*)&Cr[(long)r * (H_ * G_) + cn] = make_float2(vx, vy);
                    vals[nt * 2 + 0] = ok ? vx : -1e30f;
                    vals[nt * 2 + 1] = ok ? vy : -1e30f;
                    mx = fmaxf(mx, fmaxf(vals[nt * 2], vals[nt * 2 + 1]));
                }
                mx = fmaxf(mx, __shfl_xor_sync(0xffffffffu, mx, 1));
                mx = fmaxf(mx, __shfl_xor_sync(0xffffffffu, mx, 2));
                float s = 0.f;
#pragma unroll
                for (int i = 0; i < 8; i++) s += __expf(vals[i] - mx);
                s += __shfl_xor_sync(0xffffffffu, s, 1);
                s += __shfl_xor_sync(0xffffffffu, s, 2);
                if (tig == 0) {
                    int lr = (wm << 5) + (mt << 4) + (rr << 3) + grp;
                    redbuf[(wn << 7) + lr] = mx;
                    redbuf[256 + (wn << 7) + lr] = s;
                }
            }
        }
        __syncthreads();
        if (tid < 128) {
            float m0v = redbuf[tid],       m1v = redbuf[128 + tid];
            float s0v = redbuf[256 + tid], s1v = redbuf[384 + tid];
            float M = fmaxf(m0v, m1v);
            float S = s0v * __expf(m0v - M) + s1v * __expf(m1v - M);
            int b = m0 + tid;
            long prow = ((long)b * H_ + h) * NT_ + blockIdx.x;
            pmax[prow] = M;
            psum[prow] = S;
        }
#pragma unroll
        for (int mt = 0; mt < 2; mt++)
#pragma unroll
            for (int nt = 0; nt < 4; nt++)
#pragma unroll
                for (int r4 = 0; r4 < 4; r4++) acc[mt][nt][r4] = 0.f;
        __syncthreads();
    }
}

// ------------------------- softmax combine (LSE over tiles) ------------------
__global__ void softmax_combine(const float* __restrict__ pmax,
                                const float* __restrict__ psum,
                                float* __restrict__ rmax, float* __restrict__ rinv)
{
    int row = blockIdx.x * 8 + (threadIdx.x >> 5);
    int lane = threadIdx.x & 31;
    const float* pm = pmax + (long)row * NT_;
    const float* ps = psum + (long)row * NT_;
    float m = -1e30f, s = 0.f;
    for (int i = lane; i < NT_; i += 32) {
        float m2 = pm[i], s2 = ps[i];
        float M = fmaxf(m, m2);
        s = s * __expf(m - M) + s2 * __expf(m2 - M);
        m = M;
    }
#pragma unroll
    for (int off = 16; off; off >>= 1) {
        float m2 = __shfl_xor_sync(0xffffffffu, m, off);
        float s2 = __shfl_xor_sync(0xffffffffu, s, off);
        float M = fmaxf(m, m2);
        s = s * __expf(m - M) + s2 * __expf(m2 - M);
        m = M;
    }
    if (lane == 0) { rmax[row] = m; rinv[row] = 1.f / s; }
}

// ------------------------- softmax normalize: bf16 plane (critical path) -----
__global__ void softmax_norm_bf16(const float* __restrict__ a,
                                  __nv_bfloat16* __restrict__ ph,
                                  const float* __restrict__ rmax,
                                  const float* __restrict__ rinv)
{
    const float mx = rmax[blockIdx.x];
    const float inv = rinv[blockIdx.x];
    const float4* p = (const float4*)(a + (long)blockIdx.x * G_);
    uint32_t* h32 = (uint32_t*)(ph + (long)blockIdx.x * G_);
    const int NV = G_ / 4;
    for (int i = threadIdx.x; i < NV; i += 256) {
        float4 v = p[i];
        v.x = __expf(v.x - mx) * inv;
        v.y = __expf(v.y - mx) * inv;
        v.z = __expf(v.z - mx) * inv;
        v.w = __expf(v.w - mx) * inv;
        h32[2 * i]     = pack_bf2(v.x, v.y);
        h32[2 * i + 1] = pack_bf2(v.z, v.w);
    }
}

// ------------------------- softmax normalize: fp32 in place (side stream) ----
__global__ void softmax_norm_f32(float* __restrict__ a,
                                 const float* __restrict__ rmax,
                                 const float* __restrict__ rinv)
{
    const float mx = rmax[blockIdx.x];
    const float inv = rinv[blockIdx.x];
    float4* p = (float4*)(a + (long)blockIdx.x * G_);
    const int NV = G_ / 4;
    for (int i = threadIdx.x; i < NV; i += 256) {
        float4 v = p[i];
        v.x = __expf(v.x - mx) * inv;
        v.y = __expf(v.y - mx) * inv;
        v.z = __expf(v.z - mx) * inv;
        v.w = __expf(v.w - mx) * inv;
        p[i] = v;
    }
}

// ------------------------- fp32->bf16 hi/lo splitter -------------------------
__global__ void cvt_split(const float4* __restrict__ x,
                          __nv_bfloat162* __restrict__ hi,
                          __nv_bfloat162* __restrict__ lo, int n4)
{
    int i = blockIdx.x * blockDim.x + threadIdx.x;
    if (i >= n4) return;
    float4 v = x[i];
    float lx0, ly0, lx1, ly1;
    uint32_t h0 = pack_hi(v.x, v.y, &lx0, &ly0);
    uint32_t h1 = pack_hi(v.z, v.w, &lx1, &ly1);
    ((uint32_t*)hi)[2 * i]     = h0;
    ((uint32_t*)hi)[2 * i + 1] = h1;
    ((uint32_t*)lo)[2 * i]     = pack_bf2(lx0, ly0);
    ((uint32_t*)lo)[2 * i + 1] = pack_bf2(lx1, ly1);
}

// ------------------------- V transpose + hi/lo split -------------------------
__global__ void transpose_split(const float* __restrict__ V,
                                __nv_bfloat16* __restrict__ th,
                                __nv_bfloat16* __restrict__ tl)
{
    __shared__ float t[32][33];
    const int g0 = blockIdx.x * 32, c0 = blockIdx.y * 32;
    const int tx = threadIdx.x, ty = threadIdx.y;
#pragma unroll
    for (int j = 0; j < 4; j++) {
        int g = g0 + ty + j * 8;
        t[ty + j * 8][tx] = V[(long)g * L_ + c0 + tx];
    }
    __syncthreads();
#pragma unroll
    for (int j = 0; j < 4; j++) {
        int c = c0 + ty + j * 8;
        int g = g0 + tx;
        float x = t[tx][ty + j * 8];
        __nv_bfloat16 hi = __float2bfloat16(x);
        th[(long)c * G_ + g] = hi;
        tl[(long)c * G_ + g] = __float2bfloat16(x - __bfloat162float(hi));
    }
}

// ------------------------- split-K reduce -> planar ctx ----------------------
__global__ void reduce_ctx(const float* __restrict__ part,
                           __nv_bfloat16* __restrict__ ch,
                           __nv_bfloat16* __restrict__ cl)
{
    int idx = blockIdx.x * blockDim.x + threadIdx.x;
    if (idx >= B_ * L_) return;
    int b = idx / L_;
    int c = idx % L_;
    int h = c / HD_;
    int d = c % HD_;
    float s = 0.f;
    for (int i = 0; i < CTX_SPLITS; i++)
        s += part[(((long)h * CTX_SPLITS + i) * B_ + b) * HD_ + d];
    __nv_bfloat16 hi = __float2bfloat16(s);
    ch[idx] = hi;
    cl[idx] = __float2bfloat16(s - __bfloat162float(hi));
}

// ------------------------- LayerNorm + ReLU -> planar h ----------------------
__global__ void ln_relu(const float* __restrict__ hbuf,
                        const float* __restrict__ g, const float* __restrict__ bta,
                        __nv_bfloat16* __restrict__ hh, __nv_bfloat16* __restrict__ hl)
{
    const float* p = hbuf + (long)blockIdx.x * L_;
    __shared__ float r1[256];
    __shared__ float r2[256];
    const int t = threadIdx.x;
    float x0 = p[t], x1 = p[t + 256];
    r1[t] = x0 + x1;
    r2[t] = x0 * x0 + x1 * x1;
    __syncthreads();
    for (int s = 128; s > 0; s >>= 1) {
        if (t < s) { r1[t] += r1[t + s]; r2[t] += r2[t + s]; }
        __syncthreads();
    }
    float mu = r1[0] * (1.f / L_);
    float var = r2[0] * (1.f / L_) - mu * mu;
    float inv = rsqrtf(var + 1e-5f);
    float y0 = fmaxf((x0 - mu) * inv * g[t] + bta[t], 0.f);
    float y1 = fmaxf((x1 - mu) * inv * g[t + 256] + bta[t + 256], 0.f);
    long o = (long)blockIdx.x * L_;
    __nv_bfloat16 h0 = __float2bfloat16(y0);
    __nv_bfloat16 h1 = __float2bfloat16(y1);
    hh[o + t] = h0;
    hh[o + t + 256] = h1;
    hl[o + t] = __float2bfloat16(y0 - __bfloat162float(h0));
    hl[o + t + 256] = __float2bfloat16(y1 - __bfloat162float(h1));
}

// ------------------------- launch ---------------------------------------------
#define BF_SMEM (2 * STAGE_BYTES)

extern "C" void kernel_launch(void* const* d_in, const int* in_sizes, int n_in,
                              void* d_out, int out_size)
{
    const float* z_latent = (const float*)d_in[0];
    const float* gene_emb = (const float*)d_in[1];
    const float* Wq  = (const float*)d_in[2];
    const float* bq  = (const float*)d_in[3];
    const float* Wk  = (const float*)d_in[4];
    const float* bk  = (const float*)d_in[5];
    const float* Wv  = (const float*)d_in[6];
    const float* bv  = (const float*)d_in[7];
    const float* W1  = (const float*)d_in[8];
    const float* b1  = (const float*)d_in[9];
    const float* lng = (const float*)d_in[10];
    const float* lnb = (const float*)d_in[11];
    const float* W2  = (const float*)d_in[12];
    const float* b2  = (const float*)d_in[13];

    float* out_ga   = (float*)d_out;               // [B, G]
    float* out_attn = out_ga + (long)B_ * G_;      // [B, H, G]

    float *pV, *pCtxp, *pH, *pPmax, *pPsum, *pRmax, *pRinv;
    __nv_bfloat16 *zh, *zl, *geh, *gel, *Wqh, *Wql, *Wkh, *Wkl, *Wvh, *Wvl;
    __nv_bfloat16 *W1h, *W1l, *W2h, *W2l, *Qh, *Ql, *Kh, *Kl, *cth, *ctl, *hh, *hl;
    __nv_bfloat16 *ath, *Vth, *Vtl;
    cudaGetSymbolAddress((void**)&pV,    g_V);
    cudaGetSymbolAddress((void**)&pCtxp, g_ctxp);
    cudaGetSymbolAddress((void**)&pH,    g_h);
    cudaGetSymbolAddress((void**)&pPmax, g_pmax);
    cudaGetSymbolAddress((void**)&pPsum, g_psum);
    cudaGetSymbolAddress((void**)&pRmax, g_rmax);
    cudaGetSymbolAddress((void**)&pRinv, g_rinv);
    cudaGetSymbolAddress((void**)&zh,  g_zh);   cudaGetSymbolAddress((void**)&zl,  g_zl);
    cudaGetSymbolAddress((void**)&geh, g_geh);  cudaGetSymbolAddress((void**)&gel, g_gel);
    cudaGetSymbolAddress((void**)&Wqh, g_Wqh);  cudaGetSymbolAddress((void**)&Wql, g_Wql);
    cudaGetSymbolAddress((void**)&Wkh, g_Wkh);  cudaGetSymbolAddress((void**)&Wkl, g_Wkl);
    cudaGetSymbolAddress((void**)&Wvh, g_Wvh);  cudaGetSymbolAddress((void**)&Wvl, g_Wvl);
    cudaGetSymbolAddress((void**)&W1h, g_W1h);  cudaGetSymbolAddress((void**)&W1l, g_W1l);
    cudaGetSymbolAddress((void**)&W2h, g_W2h);  cudaGetSymbolAddress((void**)&W2l, g_W2l);
    cudaGetSymbolAddress((void**)&Qh,  g_Qh);   cudaGetSymbolAddress((void**)&Ql,  g_Ql);
    cudaGetSymbolAddress((void**)&Kh,  g_Kh);   cudaGetSymbolAddress((void**)&Kl,  g_Kl);
    cudaGetSymbolAddress((void**)&cth, g_cth);  cudaGetSymbolAddress((void**)&ctl, g_ctl);
    cudaGetSymbolAddress((void**)&hh,  g_hh);   cudaGetSymbolAddress((void**)&hl,  g_hl);
    cudaGetSymbolAddress((void**)&ath, g_ath);
    cudaGetSymbolAddress((void**)&Vth, g_Vth);  cudaGetSymbolAddress((void**)&Vtl, g_Vtl);

    cudaFuncSetAttribute(bf_gemm, cudaFuncAttributeMaxDynamicSharedMemorySize, BF_SMEM);
    cudaFuncSetAttribute(scores_gemm, cudaFuncAttributeMaxDynamicSharedMemorySize, BF_SMEM);

    static cudaStream_t sB = nullptr, sC = nullptr;
    static cudaEvent_t evGe = nullptr, evStart = nullptr, evV = nullptr, evW = nullptr;
    static cudaEvent_t evNB = nullptr, evNF = nullptr;
    if (!sB) {
        cudaStreamCreateWithFlags(&sB, cudaStreamNonBlocking);
        cudaStreamCreateWithFlags(&sC, cudaStreamNonBlocking);
        cudaEventCreateWithFlags(&evGe,    cudaEventDisableTiming);
        cudaEventCreateWithFlags(&evStart, cudaEventDisableTiming);
        cudaEventCreateWithFlags(&evV,     cudaEventDisableTiming);
        cudaEventCreateWithFlags(&evW,     cudaEventDisableTiming);
        cudaEventCreateWithFlags(&evNB,    cudaEventDisableTiming);
        cudaEventCreateWithFlags(&evNF,    cudaEventDisableTiming);
    }

    auto cvt = [&](const float* x, __nv_bfloat16* hi, __nv_bfloat16* lo, int n,
                   cudaStream_t st) {
        int n4 = n >> 2;
        cvt_split<<<(n4 + 255) / 256, 256, 0, st>>>(
            (const float4*)x, (__nv_bfloat162*)hi, (__nv_bfloat162*)lo, n4);
    };

    // ---- origin stream: ge convert first (V branch depends on it)
    cvt(gene_emb, geh, gel, G_ * GD_, 0);
    cudaEventRecord(evGe, 0);
    cudaEventRecord(evStart, 0);

    // ---- branch B: Wv cvt -> V proj -> transpose (joins before ctx)
    cudaStreamWaitEvent(sB, evGe, 0);
    cvt(Wv, Wvh, Wvl, L_ * GD_, sB);
    bf_gemm<<<dim3(8, 157, 1), 256, BF_SMEM, sB>>>(
        geh, gel, Wvh, Wvl, pV, bv, nullptr, nullptr,
        G_, L_, GD_, GD_, GD_, L_, 0, 0, 0, 0, 1, GD_, 1.f);
    transpose_split<<<dim3(G_ / 32, L_ / 32, 1), dim3(32, 8, 1), 0, sB>>>(pV, Vth, Vtl);
    cudaEventRecord(evV, sB);

    // ---- branch C: W1/W2 converts (join before step 8); later reused for
    //      the fp32 attn finalize.
    cudaStreamWaitEvent(sC, evStart, 0);
    cvt(W1, W1h, W1l, L_ * L_, sC);
    cvt(W2, W2h, W2l, G_ * L_, sC);
    cudaEventRecord(evW, sC);

    // ---- origin stream: Q/K chain
    cvt(z_latent, zh, zl, B_ * L_, 0);
    cvt(Wq, Wqh, Wql, L_ * L_, 0);
    cvt(Wk, Wkh, Wkl, L_ * GD_, 0);

    bf_gemm<<<dim3(8, 2, 1), 256, BF_SMEM>>>(
        zh, zl, Wqh, Wql, nullptr, bq, Qh, Ql,
        B_, L_, L_, L_, L_, 0, L_, 0, 0, 0, 1, L_, 1.f);

    bf_gemm<<<dim3(8, 157, 1), 256, BF_SMEM>>>(
        geh, gel, Wkh, Wkl, nullptr, bk, Kh, Kl,
        G_, L_, GD_, GD_, GD_, 0, L_, 0, 0, 0, 1, GD_, 1.f);

    scores_gemm<<<dim3(NT_, 2, 1), 256, BF_SMEM>>>(Qh, Ql, Kh, Kl, out_attn,
                                                   pPmax, pPsum);

    softmax_combine<<<B_ * H_ / 8, 256>>>(pPmax, pPsum, pRmax, pRinv);

    // critical path: bf16 attn plane only (reads raw scores, no in-place write)
    softmax_norm_bf16<<<B_ * H_, 256>>>(out_attn, ath, pRmax, pRinv);
    cudaEventRecord(evNB, 0);

    // side stream: fp32 in-place normalize of the attn output (nothing
    // downstream consumes it) — ordered after norm_bf16 to avoid the
    // read/write race, overlaps ctx/reduce/W1/ln/W2.
    cudaStreamWaitEvent(sC, evNB, 0);
    softmax_norm_f32<<<B_ * H_, 256, 0, sC>>>(out_attn, pRmax, pRinv);
    cudaEventRecord(evNF, sC);

    // ---- join V branch, then ctx (attn hi-plane only: Al = nullptr)
    cudaStreamWaitEvent(0, evV, 0);
    bf_gemm<<<dim3(1, 2, H_ * CTX_SPLITS), 256, BF_SMEM>>>(
        ath, nullptr, Vth, Vtl, pCtxp, nullptr, nullptr, nullptr,
        B_, HD_, G_, H_ * G_, G_, HD_, 0,
        G_, (long)HD_ * G_, (long)B_ * HD_, CTX_SPLITS, CTX_CHUNK, 1.f);

    reduce_ctx<<<(B_ * L_ + 255) / 256, 256>>>(pCtxp, cth, ctl);

    // ---- join W converts, then tail
    cudaStreamWaitEvent(0, evW, 0);
    bf_gemm<<<dim3(8, 2, 1), 256, BF_SMEM>>>(
        cth, ctl, W1h, W1l, pH, b1, nullptr, nullptr,
        B_, L_, L_, L_, L_, L_, 0, 0, 0, 0, 1, L_, 1.f);

    ln_relu<<<B_, 256>>>(pH, lng, lnb, hh, hl);

    bf_gemm<<<dim3(313, 2, 1), 256, BF_SMEM>>>(
        hh, hl, W2h, W2l, out_ga, b2, nullptr, nullptr,
        B_, G_, L_, L_, L_, G_, 0, 0, 0, 0, 1, L_, 1.f);

    // join the fp32-normalize side stream so capture sees all forks joined
    cudaStreamWaitEvent(0, evNF, 0);
}

// round 15
// speedup vs baseline: 1.0056x; 1.0056x over previous
#include <cuda_runtime.h>
#include <cuda_bf16.h>
#include <cstdint>
#include <math.h>

// Problem constants
#define B_   256
#define G_   20000
#define L_   512
#define GD_  256
#define H_   8
#define HD_  64
#define SCALE_ 0.125f
#define CTX_SPLITS 20
#define CTX_CHUNK  1024     // 20*1024 >= 20000; last chunk 544 (guarded)
#define NT_  313            // score n-tiles (ceil(20000/64))

// ------------------------- device scratch (static; no allocs) ---------------
__device__ float g_V[G_ * L_];
__device__ float g_ctxp[H_ * CTX_SPLITS * B_ * HD_];
__device__ float g_h[B_ * L_];
__device__ float g_pmax[B_ * H_ * NT_];
__device__ float g_psum[B_ * H_ * NT_];
__device__ float g_rmax[B_ * H_];
__device__ float g_rinv[B_ * H_];

__device__ __nv_bfloat16 g_zh[B_ * L_],  g_zl[B_ * L_];
__device__ __nv_bfloat16 g_geh[G_ * GD_], g_gel[G_ * GD_];
__device__ __nv_bfloat16 g_Wqh[L_ * L_],  g_Wql[L_ * L_];
__device__ __nv_bfloat16 g_Wkh[L_ * GD_], g_Wkl[L_ * GD_];
__device__ __nv_bfloat16 g_Wvh[L_ * GD_], g_Wvl[L_ * GD_];
__device__ __nv_bfloat16 g_W1h[L_ * L_],  g_W1l[L_ * L_];
__device__ __nv_bfloat16 g_W2h[G_ * L_],  g_W2l[G_ * L_];
__device__ __nv_bfloat16 g_Qh[B_ * L_],  g_Ql[B_ * L_];
__device__ __nv_bfloat16 g_Kh[G_ * L_],  g_Kl[G_ * L_];
__device__ __nv_bfloat16 g_cth[B_ * L_], g_ctl[B_ * L_];
__device__ __nv_bfloat16 g_hh[B_ * L_],  g_hl[B_ * L_];
__device__ __nv_bfloat16 g_ath[B_ * H_ * G_];                        // attn hi plane
__device__ __nv_bfloat16 g_Vth[L_ * G_], g_Vtl[L_ * G_];             // V^T planes

// ------------------------- helpers ------------------------------------------
__device__ __forceinline__ uint32_t smem_u32(const void* p) {
    uint32_t addr;
    asm("{ .reg .u64 tmp; cvta.to.shared.u64 tmp, %1; cvt.u32.u64 %0, tmp; }"
        : "=r"(addr) : "l"(p));
    return addr;
}

__device__ __forceinline__ void mma16816(float* c, const uint32_t* a, const uint32_t* b)
{
    asm volatile(
        "mma.sync.aligned.m16n8k16.row.col.f32.bf16.bf16.f32 "
        "{%0,%1,%2,%3}, {%4,%5,%6,%7}, {%8,%9}, {%0,%1,%2,%3};"
        : "+f"(c[0]), "+f"(c[1]), "+f"(c[2]), "+f"(c[3])
        : "r"(a[0]), "r"(a[1]), "r"(a[2]), "r"(a[3]), "r"(b[0]), "r"(b[1]));
}

__device__ __forceinline__ void ldsm4(uint32_t* r, uint32_t addr)
{
    asm volatile("ldmatrix.sync.aligned.m8n8.x4.shared.b16 {%0,%1,%2,%3}, [%4];"
                 : "=r"(r[0]), "=r"(r[1]), "=r"(r[2]), "=r"(r[3]) : "r"(addr));
}

__device__ __forceinline__ void cpa16(uint32_t dst, const void* src, int vld)
{
    asm volatile("cp.async.cg.shared.global [%0], [%1], 16, %2;"
                 :: "r"(dst), "l"(src), "r"(vld) : "memory");
}

__device__ __forceinline__ uint32_t pack_hi(float x, float y, float* rx, float* ry)
{
    __nv_bfloat16 hx = __float2bfloat16(x);
    __nv_bfloat16 hy = __float2bfloat16(y);
    *rx = x - __bfloat162float(hx);
    *ry = y - __bfloat162float(hy);
    __nv_bfloat162 p = {hx, hy};
    return *(uint32_t*)&p;
}
__device__ __forceinline__ uint32_t pack_bf2(float x, float y)
{
    __nv_bfloat162 p = {__float2bfloat16(x), __float2bfloat16(y)};
    return *(uint32_t*)&p;
}

// ------------------------- planar bf16x3 GEMM (validated core) ---------------
// Al == nullptr -> A-hi-only mode: skips Al loads and the lo*hi MMA block.
#define STAGE_BYTES 49152

__global__ __launch_bounds__(256, 2) void bf_gemm(
    const __nv_bfloat16* __restrict__ Ah, const __nv_bfloat16* __restrict__ Al,
    const __nv_bfloat16* __restrict__ Bh, const __nv_bfloat16* __restrict__ Bl,
    float* __restrict__ C, const float* __restrict__ bias,
    __nv_bfloat16* __restrict__ Ch, __nv_bfloat16* __restrict__ Cl,
    int M, int N, int K, int lda, int ldb, long ldc, int ldcp,
    long aZ, long bZ, long cZ, int kSplit, int kChunk, float alpha)
{
    extern __shared__ char smem[];
    const uint32_t smemBase = smem_u32(smem);

    const int tid = threadIdx.x;
    const int wid = tid >> 5, lane = tid & 31;
    const int wm = wid & 3, wn = wid >> 2;

    const int z = blockIdx.z;
    const int h = z / kSplit, sK = z % kSplit;
    Ah += (long)h * aZ;
    if (Al) Al += (long)h * aZ;
    Bh += (long)h * bZ; Bl += (long)h * bZ;
    if (C) C += (long)z * cZ;
    const int kStart = sK * kChunk;
    const int kEnd = min(K, kStart + kChunk);
    const int m0 = blockIdx.y * 128, n0 = blockIdx.x * 64;

    const uint32_t x7 = lane & 7;
    const uint32_t caB = (lane >> 4) & 1;
    const uint32_t cbB = (lane >> 3) & 1;
    const uint32_t aRowOff = (uint32_t)((lane & 7) + (lane & 8));
    const uint32_t bRowOff = (uint32_t)((lane & 7) + ((lane & 16) >> 1));
    uint32_t aR[2], bR[2];
#pragma unroll
    for (int mt = 0; mt < 2; mt++) aR[mt] = (uint32_t)(wm * 32 + mt * 16 + aRowOff) * 128u;
#pragma unroll
    for (int j = 0; j < 2; j++)  bR[j] = (uint32_t)(wn * 32 + j * 16 + bRowOff) * 128u;

    float acc[2][4][4];
#pragma unroll
    for (int i = 0; i < 2; i++)
#pragma unroll
        for (int j = 0; j < 4; j++)
#pragma unroll
            for (int r = 0; r < 4; r++) acc[i][j][r] = 0.f;

    const int KI = (kEnd - kStart + 63) >> 6;

    auto load_stage = [&](int it) {
        const int k0 = kStart + (it << 6);
        const uint32_t sb = smemBase + (uint32_t)(it & 1) * STAGE_BYTES;
#pragma unroll
        for (int i = 0; i < 4; i++) {
            int e = tid + (i << 8);
            int row = e >> 3, kc = e & 7;
            int gm = m0 + row, gk = k0 + (kc << 3);
            int v = (gm < M && gk + 8 <= kEnd) ? 16 : 0;
            long off = v ? ((long)gm * lda + gk) : 0;
            uint32_t dst = sb + (uint32_t)row * 128u + ((uint32_t)(kc ^ (row & 7)) << 4);
            cpa16(dst, Ah + off, v);
            if (Al) cpa16(dst + 16384, Al + off, v);
        }
#pragma unroll
        for (int i = 0; i < 2; i++) {
            int e = tid + (i << 8);
            int row = e >> 3, kc = e & 7;
            int gn = n0 + row, gk = k0 + (kc << 3);
            int v = (gn < N && gk + 8 <= kEnd) ? 16 : 0;
            long off = v ? ((long)gn * ldb + gk) : 0;
            uint32_t dst = sb + 32768u + (uint32_t)row * 128u + ((uint32_t)(kc ^ (row & 7)) << 4);
            cpa16(dst,        Bh + off, v);
            cpa16(dst + 8192, Bl + off, v);
        }
        asm volatile("cp.async.commit_group;" ::: "memory");
    };

    load_stage(0);

    for (int it = 0; it < KI; ++it) {
        asm volatile("cp.async.wait_group 0;" ::: "memory");
        __syncthreads();
        if (it + 1 < KI) load_stage(it + 1);

        const uint32_t sb = smemBase + (uint32_t)(it & 1) * STAGE_BYTES;
        uint32_t faH[2][4], faL[2][4], fb[2][4];
#pragma unroll
        for (int s = 0; s < 4; s++) {
            const uint32_t ac = (((uint32_t)(2 * s) + caB) ^ x7) << 4;
            const uint32_t bc = (((uint32_t)(2 * s) + cbB) ^ x7) << 4;
            ldsm4(faH[0], sb + aR[0] + ac);
            ldsm4(faH[1], sb + aR[1] + ac);
            ldsm4(fb[0],  sb + 32768u + bR[0] + bc);
            ldsm4(fb[1],  sb + 32768u + bR[1] + bc);
#pragma unroll
            for (int mt = 0; mt < 2; mt++)
#pragma unroll
                for (int nt = 0; nt < 4; nt++)
                    mma16816(acc[mt][nt], faH[mt], &fb[nt >> 1][(nt & 1) << 1]);
            if (Al) {
                ldsm4(faL[0], sb + 16384u + aR[0] + ac);
                ldsm4(faL[1], sb + 16384u + aR[1] + ac);
#pragma unroll
                for (int mt = 0; mt < 2; mt++)
#pragma unroll
                    for (int nt = 0; nt < 4; nt++)
                        mma16816(acc[mt][nt], faL[mt], &fb[nt >> 1][(nt & 1) << 1]);
            }
            ldsm4(fb[0], sb + 40960u + bR[0] + bc);
            ldsm4(fb[1], sb + 40960u + bR[1] + bc);
#pragma unroll
            for (int mt = 0; mt < 2; mt++)
#pragma unroll
                for (int nt = 0; nt < 4; nt++)
                    mma16816(acc[mt][nt], faH[mt], &fb[nt >> 1][(nt & 1) << 1]);
        }
        __syncthreads();
    }

    const int grp = lane >> 2, tig = lane & 3;
#pragma unroll
    for (int mt = 0; mt < 2; mt++) {
#pragma unroll
        for (int nt = 0; nt < 4; nt++) {
            int rm = m0 + (wm << 5) + (mt << 4) + grp;
            int cn = n0 + (wn << 5) + (nt << 3) + (tig << 1);
            if (cn >= N) continue;
            float bx = 0.f, by = 0.f;
            if (bias) { bx = bias[cn]; by = bias[cn + 1]; }
#pragma unroll
            for (int rr = 0; rr < 2; rr++) {
                int r = rm + rr * 8;
                if (r >= M) continue;
                float vx = acc[mt][nt][rr * 2 + 0] * alpha + bx;
                float vy = acc[mt][nt][rr * 2 + 1] * alpha + by;
                if (C) *(float2*)&C[(long)r * ldc + cn] = make_float2(vx, vy);
                if (Ch) {
                    float lx, ly;
                    uint32_t hw = pack_hi(vx, vy, &lx, &ly);
                    uint32_t lw = pack_bf2(lx, ly);
                    *(uint32_t*)&Ch[(long)r * ldcp + cn] = hw;
                    *(uint32_t*)&Cl[(long)r * ldcp + cn] = lw;
                }
            }
        }
    }
}

// ------------------------- head-looped scores GEMM + softmax partials --------
__global__ __launch_bounds__(256, 2) void scores_gemm(
    const __nv_bfloat16* __restrict__ Ah, const __nv_bfloat16* __restrict__ Al,
    const __nv_bfloat16* __restrict__ Bh, const __nv_bfloat16* __restrict__ Bl,
    float* __restrict__ C, float* __restrict__ pmax, float* __restrict__ psum)
{
    extern __shared__ char smem[];
    __shared__ float redbuf[512];
    const uint32_t smemBase = smem_u32(smem);

    const int tid = threadIdx.x;
    const int wid = tid >> 5, lane = tid & 31;
    const int wm = wid & 3, wn = wid >> 2;
    const int m0 = blockIdx.y * 128, n0 = blockIdx.x * 64;

    const uint32_t x7 = lane & 7;
    const uint32_t caB = (lane >> 4) & 1;
    const uint32_t cbB = (lane >> 3) & 1;
    const uint32_t aRowOff = (uint32_t)((lane & 7) + (lane & 8));
    const uint32_t bRowOff = (uint32_t)((lane & 7) + ((lane & 16) >> 1));
    uint32_t aR[2], bR[2];
#pragma unroll
    for (int mt = 0; mt < 2; mt++) aR[mt] = (uint32_t)(wm * 32 + mt * 16 + aRowOff) * 128u;
#pragma unroll
    for (int j = 0; j < 2; j++)  bR[j] = (uint32_t)(wn * 32 + j * 16 + bRowOff) * 128u;

    float acc[2][4][4];
#pragma unroll
    for (int i = 0; i < 2; i++)
#pragma unroll
        for (int j = 0; j < 4; j++)
#pragma unroll
            for (int r = 0; r < 4; r++) acc[i][j][r] = 0.f;

    auto load_stage = [&](int hh) {
        const int k0 = hh << 6;
        const uint32_t sb = smemBase + (uint32_t)(hh & 1) * STAGE_BYTES;
#pragma unroll
        for (int i = 0; i < 4; i++) {
            int e = tid + (i << 8);
            int row = e >> 3, kc = e & 7;
            long off = (long)(m0 + row) * L_ + k0 + (kc << 3);
            uint32_t dst = sb + (uint32_t)row * 128u + ((uint32_t)(kc ^ (row & 7)) << 4);
            cpa16(dst,         Ah + off, 16);
            cpa16(dst + 16384, Al + off, 16);
        }
#pragma unroll
        for (int i = 0; i < 2; i++) {
            int e = tid + (i << 8);
            int row = e >> 3, kc = e & 7;
            int gn = n0 + row;
            int v = (gn < G_) ? 16 : 0;
            long off = v ? ((long)gn * L_ + k0 + (kc << 3)) : 0;
            uint32_t dst = sb + 32768u + (uint32_t)row * 128u + ((uint32_t)(kc ^ (row & 7)) << 4);
            cpa16(dst,        Bh + off, v);
            cpa16(dst + 8192, Bl + off, v);
        }
        asm volatile("cp.async.commit_group;" ::: "memory");
    };

    load_stage(0);
    const int grp = lane >> 2, tig = lane & 3;

    for (int h = 0; h < H_; ++h) {
        asm volatile("cp.async.wait_group 0;" ::: "memory");
        __syncthreads();
        if (h + 1 < H_) load_stage(h + 1);

        const uint32_t sb = smemBase + (uint32_t)(h & 1) * STAGE_BYTES;
        uint32_t faH[2][4], faL[2][4], fb[2][4];
#pragma unroll
        for (int s = 0; s < 4; s++) {
            const uint32_t ac = (((uint32_t)(2 * s) + caB) ^ x7) << 4;
            const uint32_t bc = (((uint32_t)(2 * s) + cbB) ^ x7) << 4;
            ldsm4(faH[0], sb + aR[0] + ac);
            ldsm4(faH[1], sb + aR[1] + ac);
            ldsm4(faL[0], sb + 16384u + aR[0] + ac);
            ldsm4(faL[1], sb + 16384u + aR[1] + ac);
            ldsm4(fb[0],  sb + 32768u + bR[0] + bc);
            ldsm4(fb[1],  sb + 32768u + bR[1] + bc);
#pragma unroll
            for (int mt = 0; mt < 2; mt++)
#pragma unroll
                for (int nt = 0; nt < 4; nt++)
                    mma16816(acc[mt][nt], faH[mt], &fb[nt >> 1][(nt & 1) << 1]);
#pragma unroll
            for (int mt = 0; mt < 2; mt++)
#pragma unroll
                for (int nt = 0; nt < 4; nt++)
                    mma16816(acc[mt][nt], faL[mt], &fb[nt >> 1][(nt & 1) << 1]);
            ldsm4(fb[0], sb + 40960u + bR[0] + bc);
            ldsm4(fb[1], sb + 40960u + bR[1] + bc);
#pragma unroll
            for (int mt = 0; mt < 2; mt++)
#pragma unroll
                for (int nt = 0; nt < 4; nt++)
                    mma16816(acc[mt][nt], faH[mt], &fb[nt >> 1][(nt & 1) << 1]);
        }

        // ---- per-head epilogue: write raw scores + per-(row,tile) partials
        float* Cr = C + (long)h * G_;
#pragma unroll
        for (int mt = 0; mt < 2; mt++) {
#pragma unroll
            for (int rr = 0; rr < 2; rr++) {
                int r = m0 + (wm << 5) + (mt << 4) + grp + (rr << 3);
                float vals[8];
                float mx = -1e30f;
#pragma unroll
                for (int nt = 0; nt < 4; nt++) {
                    int cn = n0 + (wn << 5) + (nt << 3) + (tig << 1);
                    float vx = acc[mt][nt][rr * 2 + 0] * SCALE_;
                    float vy = acc[mt][nt][rr * 2 + 1] * SCALE_;
                    bool ok = (cn < G_);
                    if (ok) *(float2*)&Cr[(long)r * (H_ * G_) + cn] = make_float2(vx, vy);
                    vals[nt * 2 + 0] = ok ? vx : -1e30f;
                    vals[nt * 2 + 1] = ok ? vy : -1e30f;
                    mx = fmaxf(mx, fmaxf(vals[nt * 2], vals[nt * 2 + 1]));
                }
                mx = fmaxf(mx, __shfl_xor_sync(0xffffffffu, mx, 1));
                mx = fmaxf(mx, __shfl_xor_sync(0xffffffffu, mx, 2));
                float s = 0.f;
#pragma unroll
                for (int i = 0; i < 8; i++) s += __expf(vals[i] - mx);
                s += __shfl_xor_sync(0xffffffffu, s, 1);
                s += __shfl_xor_sync(0xffffffffu, s, 2);
                if (tig == 0) {
                    int lr = (wm << 5) + (mt << 4) + (rr << 3) + grp;
                    redbuf[(wn << 7) + lr] = mx;
                    redbuf[256 + (wn << 7) + lr] = s;
                }
            }
        }
        __syncthreads();
        if (tid < 128) {
            float m0v = redbuf[tid],       m1v = redbuf[128 + tid];
            float s0v = redbuf[256 + tid], s1v = redbuf[384 + tid];
            float M = fmaxf(m0v, m1v);
            float S = s0v * __expf(m0v - M) + s1v * __expf(m1v - M);
            int b = m0 + tid;
            long prow = ((long)b * H_ + h) * NT_ + blockIdx.x;
            pmax[prow] = M;
            psum[prow] = S;
        }
#pragma unroll
        for (int mt = 0; mt < 2; mt++)
#pragma unroll
            for (int nt = 0; nt < 4; nt++)
#pragma unroll
                for (int r4 = 0; r4 < 4; r4++) acc[mt][nt][r4] = 0.f;
        __syncthreads();
    }
}

// ------------------------- softmax combine (LSE over tiles) ------------------
__global__ void softmax_combine(const float* __restrict__ pmax,
                                const float* __restrict__ psum,
                                float* __restrict__ rmax, float* __restrict__ rinv)
{
    int row = blockIdx.x * 8 + (threadIdx.x >> 5);
    int lane = threadIdx.x & 31;
    const float* pm = pmax + (long)row * NT_;
    const float* ps = psum + (long)row * NT_;
    float m = -1e30f, s = 0.f;
    for (int i = lane; i < NT_; i += 32) {
        float m2 = pm[i], s2 = ps[i];
        float M = fmaxf(m, m2);
        s = s * __expf(m - M) + s2 * __expf(m2 - M);
        m = M;
    }
#pragma unroll
    for (int off = 16; off; off >>= 1) {
        float m2 = __shfl_xor_sync(0xffffffffu, m, off);
        float s2 = __shfl_xor_sync(0xffffffffu, s, off);
        float M = fmaxf(m, m2);
        s = s * __expf(m - M) + s2 * __expf(m2 - M);
        m = M;
    }
    if (lane == 0) { rmax[row] = m; rinv[row] = 1.f / s; }
}

// ------------------------- softmax normalize: bf16 plane (critical path) -----
__global__ void softmax_norm_bf16(const float* __restrict__ a,
                                  __nv_bfloat16* __restrict__ ph,
                                  const float* __restrict__ rmax,
                                  const float* __restrict__ rinv)
{
    const float mx = rmax[blockIdx.x];
    const float inv = rinv[blockIdx.x];
    const float4* p = (const float4*)(a + (long)blockIdx.x * G_);
    uint32_t* h32 = (uint32_t*)(ph + (long)blockIdx.x * G_);
    const int NV = G_ / 4;
    for (int i = threadIdx.x; i < NV; i += 256) {
        float4 v = p[i];
        v.x = __expf(v.x - mx) * inv;
        v.y = __expf(v.y - mx) * inv;
        v.z = __expf(v.z - mx) * inv;
        v.w = __expf(v.w - mx) * inv;
        h32[2 * i]     = pack_bf2(v.x, v.y);
        h32[2 * i + 1] = pack_bf2(v.z, v.w);
    }
}

// ------------------------- softmax normalize: fp32 in place (after ctx) ------
__global__ void softmax_norm_f32(float* __restrict__ a,
                                 const float* __restrict__ rmax,
                                 const float* __restrict__ rinv)
{
    const float mx = rmax[blockIdx.x];
    const float inv = rinv[blockIdx.x];
    float4* p = (float4*)(a + (long)blockIdx.x * G_);
    const int NV = G_ / 4;
    for (int i = threadIdx.x; i < NV; i += 256) {
        float4 v = p[i];
        v.x = __expf(v.x - mx) * inv;
        v.y = __expf(v.y - mx) * inv;
        v.z = __expf(v.z - mx) * inv;
        v.w = __expf(v.w - mx) * inv;
        p[i] = v;
    }
}

// ------------------------- fp32->bf16 hi/lo splitter -------------------------
__global__ void cvt_split(const float4* __restrict__ x,
                          __nv_bfloat162* __restrict__ hi,
                          __nv_bfloat162* __restrict__ lo, int n4)
{
    int i = blockIdx.x * blockDim.x + threadIdx.x;
    if (i >= n4) return;
    float4 v = x[i];
    float lx0, ly0, lx1, ly1;
    uint32_t h0 = pack_hi(v.x, v.y, &lx0, &ly0);
    uint32_t h1 = pack_hi(v.z, v.w, &lx1, &ly1);
    ((uint32_t*)hi)[2 * i]     = h0;
    ((uint32_t*)hi)[2 * i + 1] = h1;
    ((uint32_t*)lo)[2 * i]     = pack_bf2(lx0, ly0);
    ((uint32_t*)lo)[2 * i + 1] = pack_bf2(lx1, ly1);
}

// ------------------------- V transpose + hi/lo split -------------------------
__global__ void transpose_split(const float* __restrict__ V,
                                __nv_bfloat16* __restrict__ th,
                                __nv_bfloat16* __restrict__ tl)
{
    __shared__ float t[32][33];
    const int g0 = blockIdx.x * 32, c0 = blockIdx.y * 32;
    const int tx = threadIdx.x, ty = threadIdx.y;
#pragma unroll
    for (int j = 0; j < 4; j++) {
        int g = g0 + ty + j * 8;
        t[ty + j * 8][tx] = V[(long)g * L_ + c0 + tx];
    }
    __syncthreads();
#pragma unroll
    for (int j = 0; j < 4; j++) {
        int c = c0 + ty + j * 8;
        int g = g0 + tx;
        float x = t[tx][ty + j * 8];
        __nv_bfloat16 hi = __float2bfloat16(x);
        th[(long)c * G_ + g] = hi;
        tl[(long)c * G_ + g] = __float2bfloat16(x - __bfloat162float(hi));
    }
}

// ------------------------- split-K reduce -> planar ctx ----------------------
__global__ void reduce_ctx(const float* __restrict__ part,
                           __nv_bfloat16* __restrict__ ch,
                           __nv_bfloat16* __restrict__ cl)
{
    int idx = blockIdx.x * blockDim.x + threadIdx.x;
    if (idx >= B_ * L_) return;
    int b = idx / L_;
    int c = idx % L_;
    int h = c / HD_;
    int d = c % HD_;
    float s = 0.f;
    for (int i = 0; i < CTX_SPLITS; i++)
        s += part[(((long)h * CTX_SPLITS + i) * B_ + b) * HD_ + d];
    __nv_bfloat16 hi = __float2bfloat16(s);
    ch[idx] = hi;
    cl[idx] = __float2bfloat16(s - __bfloat162float(hi));
}

// ------------------------- LayerNorm + ReLU -> planar h ----------------------
__global__ void ln_relu(const float* __restrict__ hbuf,
                        const float* __restrict__ g, const float* __restrict__ bta,
                        __nv_bfloat16* __restrict__ hh, __nv_bfloat16* __restrict__ hl)
{
    const float* p = hbuf + (long)blockIdx.x * L_;
    __shared__ float r1[256];
    __shared__ float r2[256];
    const int t = threadIdx.x;
    float x0 = p[t], x1 = p[t + 256];
    r1[t] = x0 + x1;
    r2[t] = x0 * x0 + x1 * x1;
    __syncthreads();
    for (int s = 128; s > 0; s >>= 1) {
        if (t < s) { r1[t] += r1[t + s]; r2[t] += r2[t + s]; }
        __syncthreads();
    }
    float mu = r1[0] * (1.f / L_);
    float var = r2[0] * (1.f / L_) - mu * mu;
    float inv = rsqrtf(var + 1e-5f);
    float y0 = fmaxf((x0 - mu) * inv * g[t] + bta[t], 0.f);
    float y1 = fmaxf((x1 - mu) * inv * g[t + 256] + bta[t + 256], 0.f);
    long o = (long)blockIdx.x * L_;
    __nv_bfloat16 h0 = __float2bfloat16(y0);
    __nv_bfloat16 h1 = __float2bfloat16(y1);
    hh[o + t] = h0;
    hh[o + t + 256] = h1;
    hl[o + t] = __float2bfloat16(y0 - __bfloat162float(h0));
    hl[o + t + 256] = __float2bfloat16(y1 - __bfloat162float(h1));
}

// ------------------------- launch ---------------------------------------------
#define BF_SMEM (2 * STAGE_BYTES)

extern "C" void kernel_launch(void* const* d_in, const int* in_sizes, int n_in,
                              void* d_out, int out_size)
{
    const float* z_latent = (const float*)d_in[0];
    const float* gene_emb = (const float*)d_in[1];
    const float* Wq  = (const float*)d_in[2];
    const float* bq  = (const float*)d_in[3];
    const float* Wk  = (const float*)d_in[4];
    const float* bk  = (const float*)d_in[5];
    const float* Wv  = (const float*)d_in[6];
    const float* bv  = (const float*)d_in[7];
    const float* W1  = (const float*)d_in[8];
    const float* b1  = (const float*)d_in[9];
    const float* lng = (const float*)d_in[10];
    const float* lnb = (const float*)d_in[11];
    const float* W2  = (const float*)d_in[12];
    const float* b2  = (const float*)d_in[13];

    float* out_ga   = (float*)d_out;               // [B, G]
    float* out_attn = out_ga + (long)B_ * G_;      // [B, H, G]

    float *pV, *pCtxp, *pH, *pPmax, *pPsum, *pRmax, *pRinv;
    __nv_bfloat16 *zh, *zl, *geh, *gel, *Wqh, *Wql, *Wkh, *Wkl, *Wvh, *Wvl;
    __nv_bfloat16 *W1h, *W1l, *W2h, *W2l, *Qh, *Ql, *Kh, *Kl, *cth, *ctl, *hh, *hl;
    __nv_bfloat16 *ath, *Vth, *Vtl;
    cudaGetSymbolAddress((void**)&pV,    g_V);
    cudaGetSymbolAddress((void**)&pCtxp, g_ctxp);
    cudaGetSymbolAddress((void**)&pH,    g_h);
    cudaGetSymbolAddress((void**)&pPmax, g_pmax);
    cudaGetSymbolAddress((void**)&pPsum, g_psum);
    cudaGetSymbolAddress((void**)&pRmax, g_rmax);
    cudaGetSymbolAddress((void**)&pRinv, g_rinv);
    cudaGetSymbolAddress((void**)&zh,  g_zh);   cudaGetSymbolAddress((void**)&zl,  g_zl);
    cudaGetSymbolAddress((void**)&geh, g_geh);  cudaGetSymbolAddress((void**)&gel, g_gel);
    cudaGetSymbolAddress((void**)&Wqh, g_Wqh);  cudaGetSymbolAddress((void**)&Wql, g_Wql);
    cudaGetSymbolAddress((void**)&Wkh, g_Wkh);  cudaGetSymbolAddress((void**)&Wkl, g_Wkl);
    cudaGetSymbolAddress((void**)&Wvh, g_Wvh);  cudaGetSymbolAddress((void**)&Wvl, g_Wvl);
    cudaGetSymbolAddress((void**)&W1h, g_W1h);  cudaGetSymbolAddress((void**)&W1l, g_W1l);
    cudaGetSymbolAddress((void**)&W2h, g_W2h);  cudaGetSymbolAddress((void**)&W2l, g_W2l);
    cudaGetSymbolAddress((void**)&Qh,  g_Qh);   cudaGetSymbolAddress((void**)&Ql,  g_Ql);
    cudaGetSymbolAddress((void**)&Kh,  g_Kh);   cudaGetSymbolAddress((void**)&Kl,  g_Kl);
    cudaGetSymbolAddress((void**)&cth, g_cth);  cudaGetSymbolAddress((void**)&ctl, g_ctl);
    cudaGetSymbolAddress((void**)&hh,  g_hh);   cudaGetSymbolAddress((void**)&hl,  g_hl);
    cudaGetSymbolAddress((void**)&ath, g_ath);
    cudaGetSymbolAddress((void**)&Vth, g_Vth);  cudaGetSymbolAddress((void**)&Vtl, g_Vtl);

    cudaFuncSetAttribute(bf_gemm, cudaFuncAttributeMaxDynamicSharedMemorySize, BF_SMEM);
    cudaFuncSetAttribute(scores_gemm, cudaFuncAttributeMaxDynamicSharedMemorySize, BF_SMEM);

    static cudaStream_t sB = nullptr, sC = nullptr;
    static cudaEvent_t evGe = nullptr, evStart = nullptr, evV = nullptr, evW = nullptr;
    static cudaEvent_t evCtx = nullptr, evNF = nullptr;
    if (!sB) {
        cudaStreamCreateWithFlags(&sB, cudaStreamNonBlocking);
        cudaStreamCreateWithFlags(&sC, cudaStreamNonBlocking);
        cudaEventCreateWithFlags(&evGe,    cudaEventDisableTiming);
        cudaEventCreateWithFlags(&evStart, cudaEventDisableTiming);
        cudaEventCreateWithFlags(&evV,     cudaEventDisableTiming);
        cudaEventCreateWithFlags(&evW,     cudaEventDisableTiming);
        cudaEventCreateWithFlags(&evCtx,   cudaEventDisableTiming);
        cudaEventCreateWithFlags(&evNF,    cudaEventDisableTiming);
    }

    auto cvt = [&](const float* x, __nv_bfloat16* hi, __nv_bfloat16* lo, int n,
                   cudaStream_t st) {
        int n4 = n >> 2;
        cvt_split<<<(n4 + 255) / 256, 256, 0, st>>>(
            (const float4*)x, (__nv_bfloat162*)hi, (__nv_bfloat162*)lo, n4);
    };

    // ---- origin stream: ge convert first (V branch depends on it)
    cvt(gene_emb, geh, gel, G_ * GD_, 0);
    cudaEventRecord(evGe, 0);
    cudaEventRecord(evStart, 0);

    // ---- branch B: Wv cvt -> V proj -> transpose (joins before ctx)
    cudaStreamWaitEvent(sB, evGe, 0);
    cvt(Wv, Wvh, Wvl, L_ * GD_, sB);
    bf_gemm<<<dim3(8, 157, 1), 256, BF_SMEM, sB>>>(
        geh, gel, Wvh, Wvl, pV, bv, nullptr, nullptr,
        G_, L_, GD_, GD_, GD_, L_, 0, 0, 0, 0, 1, GD_, 1.f);
    transpose_split<<<dim3(G_ / 32, L_ / 32, 1), dim3(32, 8, 1), 0, sB>>>(pV, Vth, Vtl);
    cudaEventRecord(evV, sB);

    // ---- branch C: W1/W2 converts (join before step 8)
    cudaStreamWaitEvent(sC, evStart, 0);
    cvt(W1, W1h, W1l, L_ * L_, sC);
    cvt(W2, W2h, W2l, G_ * L_, sC);
    cudaEventRecord(evW, sC);

    // ---- origin stream: Q/K chain
    cvt(z_latent, zh, zl, B_ * L_, 0);
    cvt(Wq, Wqh, Wql, L_ * L_, 0);
    cvt(Wk, Wkh, Wkl, L_ * GD_, 0);

    bf_gemm<<<dim3(8, 2, 1), 256, BF_SMEM>>>(
        zh, zl, Wqh, Wql, nullptr, bq, Qh, Ql,
        B_, L_, L_, L_, L_, 0, L_, 0, 0, 0, 1, L_, 1.f);

    bf_gemm<<<dim3(8, 157, 1), 256, BF_SMEM>>>(
        geh, gel, Wkh, Wkl, nullptr, bk, Kh, Kl,
        G_, L_, GD_, GD_, GD_, 0, L_, 0, 0, 0, 1, GD_, 1.f);

    scores_gemm<<<dim3(NT_, 2, 1), 256, BF_SMEM>>>(Qh, Ql, Kh, Kl, out_attn,
                                                   pPmax, pPsum);

    softmax_combine<<<B_ * H_ / 8, 256>>>(pPmax, pPsum, pRmax, pRinv);

    // critical path: bf16 attn plane only (reads raw scores, no in-place write)
    softmax_norm_bf16<<<B_ * H_, 256>>>(out_attn, ath, pRmax, pRinv);

    // ---- join V branch, then ctx (attn hi-plane only: Al = nullptr)
    cudaStreamWaitEvent(0, evV, 0);
    bf_gemm<<<dim3(1, 2, H_ * CTX_SPLITS), 256, BF_SMEM>>>(
        ath, nullptr, Vth, Vtl, pCtxp, nullptr, nullptr, nullptr,
        B_, HD_, G_, H_ * G_, G_, HD_, 0,
        G_, (long)HD_ * G_, (long)B_ * HD_, CTX_SPLITS, CTX_CHUNK, 1.f);
    cudaEventRecord(evCtx, 0);

    // side stream: fp32 in-place attn finalize AFTER ctx is done (avoids
    // bandwidth contention with the ctx GEMM; overlaps reduce/W1/ln/W2).
    // evCtx also orders it after softmax_norm_bf16's read of the raw scores.
    cudaStreamWaitEvent(sC, evCtx, 0);
    softmax_norm_f32<<<B_ * H_, 256, 0, sC>>>(out_attn, pRmax, pRinv);
    cudaEventRecord(evNF, sC);

    reduce_ctx<<<(B_ * L_ + 255) / 256, 256>>>(pCtxp, cth, ctl);

    // ---- join W converts, then tail
    cudaStreamWaitEvent(0, evW, 0);
    bf_gemm<<<dim3(8, 2, 1), 256, BF_SMEM>>>(
        cth, ctl, W1h, W1l, pH, b1, nullptr, nullptr,
        B_, L_, L_, L_, L_, L_, 0, 0, 0, 0, 1, L_, 1.f);

    ln_relu<<<B_, 256>>>(pH, lng, lnb, hh, hl);

    bf_gemm<<<dim3(313, 2, 1), 256, BF_SMEM>>>(
        hh, hl, W2h, W2l, out_ga, b2, nullptr, nullptr,
        B_, G_, L_, L_, L_, G_, 0, 0, 0, 0, 1, L_, 1.f);

    // join the fp32-normalize side stream so capture sees all forks joined
    cudaStreamWaitEvent(0, evNF, 0);
}

// round 16
// speedup vs baseline: 1.0082x; 1.0027x over previous
#include <cuda_runtime.h>
#include <cuda_bf16.h>
#include <cstdint>
#include <math.h>

// Problem constants
#define B_   256
#define G_   20000
#define L_   512
#define GD_  256
#define H_   8
#define HD_  64
#define SCALE_ 0.125f
#define CTX_SPLITS 20
#define CTX_CHUNK  1024     // 20*1024 >= 20000; last chunk 544 (guarded)
#define NT_  313            // score n-tiles (ceil(20000/64))

// ------------------------- device scratch (static; no allocs) ---------------
__device__ float g_V[G_ * L_];
__device__ float g_ctxp[H_ * CTX_SPLITS * B_ * HD_];
__device__ float g_h[B_ * L_];
__device__ float g_pmax[B_ * H_ * NT_];
__device__ float g_psum[B_ * H_ * NT_];
__device__ float g_rmax[B_ * H_];
__device__ float g_rinv[B_ * H_];

__device__ __nv_bfloat16 g_zh[B_ * L_],  g_zl[B_ * L_];
__device__ __nv_bfloat16 g_geh[G_ * GD_], g_gel[G_ * GD_];
__device__ __nv_bfloat16 g_Wqh[L_ * L_],  g_Wql[L_ * L_];
__device__ __nv_bfloat16 g_Wkh[L_ * GD_], g_Wkl[L_ * GD_];
__device__ __nv_bfloat16 g_Wvh[L_ * GD_], g_Wvl[L_ * GD_];
__device__ __nv_bfloat16 g_W1h[L_ * L_],  g_W1l[L_ * L_];
__device__ __nv_bfloat16 g_W2h[G_ * L_],  g_W2l[G_ * L_];
__device__ __nv_bfloat16 g_Qh[B_ * L_],  g_Ql[B_ * L_];
__device__ __nv_bfloat16 g_Kh[G_ * L_],  g_Kl[G_ * L_];
__device__ __nv_bfloat16 g_cth[B_ * L_], g_ctl[B_ * L_];
__device__ __nv_bfloat16 g_hh[B_ * L_],  g_hl[B_ * L_];
__device__ __nv_bfloat16 g_ath[B_ * H_ * G_];                        // attn hi plane
__device__ __nv_bfloat16 g_Vth[L_ * G_], g_Vtl[L_ * G_];             // V^T planes

// ------------------------- helpers ------------------------------------------
__device__ __forceinline__ uint32_t smem_u32(const void* p) {
    uint32_t addr;
    asm("{ .reg .u64 tmp; cvta.to.shared.u64 tmp, %1; cvt.u32.u64 %0, tmp; }"
        : "=r"(addr) : "l"(p));
    return addr;
}

__device__ __forceinline__ void mma16816(float* c, const uint32_t* a, const uint32_t* b)
{
    asm volatile(
        "mma.sync.aligned.m16n8k16.row.col.f32.bf16.bf16.f32 "
        "{%0,%1,%2,%3}, {%4,%5,%6,%7}, {%8,%9}, {%0,%1,%2,%3};"
        : "+f"(c[0]), "+f"(c[1]), "+f"(c[2]), "+f"(c[3])
        : "r"(a[0]), "r"(a[1]), "r"(a[2]), "r"(a[3]), "r"(b[0]), "r"(b[1]));
}

__device__ __forceinline__ void ldsm4(uint32_t* r, uint32_t addr)
{
    asm volatile("ldmatrix.sync.aligned.m8n8.x4.shared.b16 {%0,%1,%2,%3}, [%4];"
                 : "=r"(r[0]), "=r"(r[1]), "=r"(r[2]), "=r"(r[3]) : "r"(addr));
}

__device__ __forceinline__ void cpa16(uint32_t dst, const void* src, int vld)
{
    asm volatile("cp.async.cg.shared.global [%0], [%1], 16, %2;"
                 :: "r"(dst), "l"(src), "r"(vld) : "memory");
}

__device__ __forceinline__ uint32_t pack_hi(float x, float y, float* rx, float* ry)
{
    __nv_bfloat16 hx = __float2bfloat16(x);
    __nv_bfloat16 hy = __float2bfloat16(y);
    *rx = x - __bfloat162float(hx);
    *ry = y - __bfloat162float(hy);
    __nv_bfloat162 p = {hx, hy};
    return *(uint32_t*)&p;
}
__device__ __forceinline__ uint32_t pack_bf2(float x, float y)
{
    __nv_bfloat162 p = {__float2bfloat16(x), __float2bfloat16(y)};
    return *(uint32_t*)&p;
}

// ------------------------- planar bf16x3 GEMM (validated core) ---------------
// Al == nullptr -> A-hi-only mode: skips Al loads and the lo*hi MMA block.
#define STAGE_BYTES 49152

__global__ __launch_bounds__(256, 2) void bf_gemm(
    const __nv_bfloat16* __restrict__ Ah, const __nv_bfloat16* __restrict__ Al,
    const __nv_bfloat16* __restrict__ Bh, const __nv_bfloat16* __restrict__ Bl,
    float* __restrict__ C, const float* __restrict__ bias,
    __nv_bfloat16* __restrict__ Ch, __nv_bfloat16* __restrict__ Cl,
    int M, int N, int K, int lda, int ldb, long ldc, int ldcp,
    long aZ, long bZ, long cZ, int kSplit, int kChunk, float alpha)
{
    extern __shared__ char smem[];
    const uint32_t smemBase = smem_u32(smem);

    const int tid = threadIdx.x;
    const int wid = tid >> 5, lane = tid & 31;
    const int wm = wid & 3, wn = wid >> 2;

    const int z = blockIdx.z;
    const int h = z / kSplit, sK = z % kSplit;
    Ah += (long)h * aZ;
    if (Al) Al += (long)h * aZ;
    Bh += (long)h * bZ; Bl += (long)h * bZ;
    if (C) C += (long)z * cZ;
    const int kStart = sK * kChunk;
    const int kEnd = min(K, kStart + kChunk);
    const int m0 = blockIdx.y * 128, n0 = blockIdx.x * 64;

    const uint32_t x7 = lane & 7;
    const uint32_t caB = (lane >> 4) & 1;
    const uint32_t cbB = (lane >> 3) & 1;
    const uint32_t aRowOff = (uint32_t)((lane & 7) + (lane & 8));
    const uint32_t bRowOff = (uint32_t)((lane & 7) + ((lane & 16) >> 1));
    uint32_t aR[2], bR[2];
#pragma unroll
    for (int mt = 0; mt < 2; mt++) aR[mt] = (uint32_t)(wm * 32 + mt * 16 + aRowOff) * 128u;
#pragma unroll
    for (int j = 0; j < 2; j++)  bR[j] = (uint32_t)(wn * 32 + j * 16 + bRowOff) * 128u;

    float acc[2][4][4];
#pragma unroll
    for (int i = 0; i < 2; i++)
#pragma unroll
        for (int j = 0; j < 4; j++)
#pragma unroll
            for (int r = 0; r < 4; r++) acc[i][j][r] = 0.f;

    const int KI = (kEnd - kStart + 63) >> 6;

    auto load_stage = [&](int it) {
        const int k0 = kStart + (it << 6);
        const uint32_t sb = smemBase + (uint32_t)(it & 1) * STAGE_BYTES;
#pragma unroll
        for (int i = 0; i < 4; i++) {
            int e = tid + (i << 8);
            int row = e >> 3, kc = e & 7;
            int gm = m0 + row, gk = k0 + (kc << 3);
            int v = (gm < M && gk + 8 <= kEnd) ? 16 : 0;
            long off = v ? ((long)gm * lda + gk) : 0;
            uint32_t dst = sb + (uint32_t)row * 128u + ((uint32_t)(kc ^ (row & 7)) << 4);
            cpa16(dst, Ah + off, v);
            if (Al) cpa16(dst + 16384, Al + off, v);
        }
#pragma unroll
        for (int i = 0; i < 2; i++) {
            int e = tid + (i << 8);
            int row = e >> 3, kc = e & 7;
            int gn = n0 + row, gk = k0 + (kc << 3);
            int v = (gn < N && gk + 8 <= kEnd) ? 16 : 0;
            long off = v ? ((long)gn * ldb + gk) : 0;
            uint32_t dst = sb + 32768u + (uint32_t)row * 128u + ((uint32_t)(kc ^ (row & 7)) << 4);
            cpa16(dst,        Bh + off, v);
            cpa16(dst + 8192, Bl + off, v);
        }
        asm volatile("cp.async.commit_group;" ::: "memory");
    };

    load_stage(0);

    for (int it = 0; it < KI; ++it) {
        asm volatile("cp.async.wait_group 0;" ::: "memory");
        __syncthreads();
        if (it + 1 < KI) load_stage(it + 1);

        const uint32_t sb = smemBase + (uint32_t)(it & 1) * STAGE_BYTES;
        uint32_t faH[2][4], faL[2][4], fb[2][4];
#pragma unroll
        for (int s = 0; s < 4; s++) {
            const uint32_t ac = (((uint32_t)(2 * s) + caB) ^ x7) << 4;
            const uint32_t bc = (((uint32_t)(2 * s) + cbB) ^ x7) << 4;
            ldsm4(faH[0], sb + aR[0] + ac);
            ldsm4(faH[1], sb + aR[1] + ac);
            ldsm4(fb[0],  sb + 32768u + bR[0] + bc);
            ldsm4(fb[1],  sb + 32768u + bR[1] + bc);
#pragma unroll
            for (int mt = 0; mt < 2; mt++)
#pragma unroll
                for (int nt = 0; nt < 4; nt++)
                    mma16816(acc[mt][nt], faH[mt], &fb[nt >> 1][(nt & 1) << 1]);
            if (Al) {
                ldsm4(faL[0], sb + 16384u + aR[0] + ac);
                ldsm4(faL[1], sb + 16384u + aR[1] + ac);
#pragma unroll
                for (int mt = 0; mt < 2; mt++)
#pragma unroll
                    for (int nt = 0; nt < 4; nt++)
                        mma16816(acc[mt][nt], faL[mt], &fb[nt >> 1][(nt & 1) << 1]);
            }
            ldsm4(fb[0], sb + 40960u + bR[0] + bc);
            ldsm4(fb[1], sb + 40960u + bR[1] + bc);
#pragma unroll
            for (int mt = 0; mt < 2; mt++)
#pragma unroll
                for (int nt = 0; nt < 4; nt++)
                    mma16816(acc[mt][nt], faH[mt], &fb[nt >> 1][(nt & 1) << 1]);
        }
        __syncthreads();
    }

    const int grp = lane >> 2, tig = lane & 3;
#pragma unroll
    for (int mt = 0; mt < 2; mt++) {
#pragma unroll
        for (int nt = 0; nt < 4; nt++) {
            int rm = m0 + (wm << 5) + (mt << 4) + grp;
            int cn = n0 + (wn << 5) + (nt << 3) + (tig << 1);
            if (cn >= N) continue;
            float bx = 0.f, by = 0.f;
            if (bias) { bx = bias[cn]; by = bias[cn + 1]; }
#pragma unroll
            for (int rr = 0; rr < 2; rr++) {
                int r = rm + rr * 8;
                if (r >= M) continue;
                float vx = acc[mt][nt][rr * 2 + 0] * alpha + bx;
                float vy = acc[mt][nt][rr * 2 + 1] * alpha + by;
                if (C) *(float2*)&C[(long)r * ldc + cn] = make_float2(vx, vy);
                if (Ch) {
                    float lx, ly;
                    uint32_t hw = pack_hi(vx, vy, &lx, &ly);
                    uint32_t lw = pack_bf2(lx, ly);
                    *(uint32_t*)&Ch[(long)r * ldcp + cn] = hw;
                    *(uint32_t*)&Cl[(long)r * ldcp + cn] = lw;
                }
            }
        }
    }
}

// ------------------------- head-looped scores GEMM + softmax partials --------
__global__ __launch_bounds__(256, 2) void scores_gemm(
    const __nv_bfloat16* __restrict__ Ah, const __nv_bfloat16* __restrict__ Al,
    const __nv_bfloat16* __restrict__ Bh, const __nv_bfloat16* __restrict__ Bl,
    float* __restrict__ C, float* __restrict__ pmax, float* __restrict__ psum)
{
    extern __shared__ char smem[];
    __shared__ float redbuf[512];
    const uint32_t smemBase = smem_u32(smem);

    const int tid = threadIdx.x;
    const int wid = tid >> 5, lane = tid & 31;
    const int wm = wid & 3, wn = wid >> 2;
    const int m0 = blockIdx.y * 128, n0 = blockIdx.x * 64;

    const uint32_t x7 = lane & 7;
    const uint32_t caB = (lane >> 4) & 1;
    const uint32_t cbB = (lane >> 3) & 1;
    const uint32_t aRowOff = (uint32_t)((lane & 7) + (lane & 8));
    const uint32_t bRowOff = (uint32_t)((lane & 7) + ((lane & 16) >> 1));
    uint32_t aR[2], bR[2];
#pragma unroll
    for (int mt = 0; mt < 2; mt++) aR[mt] = (uint32_t)(wm * 32 + mt * 16 + aRowOff) * 128u;
#pragma unroll
    for (int j = 0; j < 2; j++)  bR[j] = (uint32_t)(wn * 32 + j * 16 + bRowOff) * 128u;

    float acc[2][4][4];
#pragma unroll
    for (int i = 0; i < 2; i++)
#pragma unroll
        for (int j = 0; j < 4; j++)
#pragma unroll
            for (int r = 0; r < 4; r++) acc[i][j][r] = 0.f;

    auto load_stage = [&](int hh) {
        const int k0 = hh << 6;
        const uint32_t sb = smemBase + (uint32_t)(hh & 1) * STAGE_BYTES;
#pragma unroll
        for (int i = 0; i < 4; i++) {
            int e = tid + (i << 8);
            int row = e >> 3, kc = e & 7;
            long off = (long)(m0 + row) * L_ + k0 + (kc << 3);
            uint32_t dst = sb + (uint32_t)row * 128u + ((uint32_t)(kc ^ (row & 7)) << 4);
            cpa16(dst,         Ah + off, 16);
            cpa16(dst + 16384, Al + off, 16);
        }
#pragma unroll
        for (int i = 0; i < 2; i++) {
            int e = tid + (i << 8);
            int row = e >> 3, kc = e & 7;
            int gn = n0 + row;
            int v = (gn < G_) ? 16 : 0;
            long off = v ? ((long)gn * L_ + k0 + (kc << 3)) : 0;
            uint32_t dst = sb + 32768u + (uint32_t)row * 128u + ((uint32_t)(kc ^ (row & 7)) << 4);
            cpa16(dst,        Bh + off, v);
            cpa16(dst + 8192, Bl + off, v);
        }
        asm volatile("cp.async.commit_group;" ::: "memory");
    };

    load_stage(0);
    const int grp = lane >> 2, tig = lane & 3;

    for (int h = 0; h < H_; ++h) {
        asm volatile("cp.async.wait_group 0;" ::: "memory");
        __syncthreads();
        if (h + 1 < H_) load_stage(h + 1);

        const uint32_t sb = smemBase + (uint32_t)(h & 1) * STAGE_BYTES;
        uint32_t faH[2][4], faL[2][4], fb[2][4];
#pragma unroll
        for (int s = 0; s < 4; s++) {
            const uint32_t ac = (((uint32_t)(2 * s) + caB) ^ x7) << 4;
            const uint32_t bc = (((uint32_t)(2 * s) + cbB) ^ x7) << 4;
            ldsm4(faH[0], sb + aR[0] + ac);
            ldsm4(faH[1], sb + aR[1] + ac);
            ldsm4(faL[0], sb + 16384u + aR[0] + ac);
            ldsm4(faL[1], sb + 16384u + aR[1] + ac);
            ldsm4(fb[0],  sb + 32768u + bR[0] + bc);
            ldsm4(fb[1],  sb + 32768u + bR[1] + bc);
#pragma unroll
            for (int mt = 0; mt < 2; mt++)
#pragma unroll
                for (int nt = 0; nt < 4; nt++)
                    mma16816(acc[mt][nt], faH[mt], &fb[nt >> 1][(nt & 1) << 1]);
#pragma unroll
            for (int mt = 0; mt < 2; mt++)
#pragma unroll
                for (int nt = 0; nt < 4; nt++)
                    mma16816(acc[mt][nt], faL[mt], &fb[nt >> 1][(nt & 1) << 1]);
            ldsm4(fb[0], sb + 40960u + bR[0] + bc);
            ldsm4(fb[1], sb + 40960u + bR[1] + bc);
#pragma unroll
            for (int mt = 0; mt < 2; mt++)
#pragma unroll
                for (int nt = 0; nt < 4; nt++)
                    mma16816(acc[mt][nt], faH[mt], &fb[nt >> 1][(nt & 1) << 1]);
        }

        // ---- per-head epilogue: write raw scores + per-(row,tile) partials
        float* Cr = C + (long)h * G_;
#pragma unroll
        for (int mt = 0; mt < 2; mt++) {
#pragma unroll
            for (int rr = 0; rr < 2; rr++) {
                int r = m0 + (wm << 5) + (mt << 4) + grp + (rr << 3);
                float vals[8];
                float mx = -1e30f;
#pragma unroll
                for (int nt = 0; nt < 4; nt++) {
                    int cn = n0 + (wn << 5) + (nt << 3) + (tig << 1);
                    float vx = acc[mt][nt][rr * 2 + 0] * SCALE_;
                    float vy = acc[mt][nt][rr * 2 + 1] * SCALE_;
                    bool ok = (cn < G_);
                    if (ok) *(float2*)&Cr[(long)r * (H_ * G_) + cn] = make_float2(vx, vy);
                    vals[nt * 2 + 0] = ok ? vx : -1e30f;
                    vals[nt * 2 + 1] = ok ? vy : -1e30f;
                    mx = fmaxf(mx, fmaxf(vals[nt * 2], vals[nt * 2 + 1]));
                }
                mx = fmaxf(mx, __shfl_xor_sync(0xffffffffu, mx, 1));
                mx = fmaxf(mx, __shfl_xor_sync(0xffffffffu, mx, 2));
                float s = 0.f;
#pragma unroll
                for (int i = 0; i < 8; i++) s += __expf(vals[i] - mx);
                s += __shfl_xor_sync(0xffffffffu, s, 1);
                s += __shfl_xor_sync(0xffffffffu, s, 2);
                if (tig == 0) {
                    int lr = (wm << 5) + (mt << 4) + (rr << 3) + grp;
                    redbuf[(wn << 7) + lr] = mx;
                    redbuf[256 + (wn << 7) + lr] = s;
                }
            }
        }
        __syncthreads();
        if (tid < 128) {
            float m0v = redbuf[tid],       m1v = redbuf[128 + tid];
            float s0v = redbuf[256 + tid], s1v = redbuf[384 + tid];
            float M = fmaxf(m0v, m1v);
            float S = s0v * __expf(m0v - M) + s1v * __expf(m1v - M);
            int b = m0 + tid;
            long prow = ((long)b * H_ + h) * NT_ + blockIdx.x;
            pmax[prow] = M;
            psum[prow] = S;
        }
#pragma unroll
        for (int mt = 0; mt < 2; mt++)
#pragma unroll
            for (int nt = 0; nt < 4; nt++)
#pragma unroll
                for (int r4 = 0; r4 < 4; r4++) acc[mt][nt][r4] = 0.f;
        __syncthreads();
    }
}

// ------------------------- softmax combine (LSE over tiles) ------------------
__global__ void softmax_combine(const float* __restrict__ pmax,
                                const float* __restrict__ psum,
                                float* __restrict__ rmax, float* __restrict__ rinv)
{
    int row = blockIdx.x * 8 + (threadIdx.x >> 5);
    int lane = threadIdx.x & 31;
    const float* pm = pmax + (long)row * NT_;
    const float* ps = psum + (long)row * NT_;
    float m = -1e30f, s = 0.f;
    for (int i = lane; i < NT_; i += 32) {
        float m2 = pm[i], s2 = ps[i];
        float M = fmaxf(m, m2);
        s = s * __expf(m - M) + s2 * __expf(m2 - M);
        m = M;
    }
#pragma unroll
    for (int off = 16; off; off >>= 1) {
        float m2 = __shfl_xor_sync(0xffffffffu, m, off);
        float s2 = __shfl_xor_sync(0xffffffffu, s, off);
        float M = fmaxf(m, m2);
        s = s * __expf(m - M) + s2 * __expf(m2 - M);
        m = M;
    }
    if (lane == 0) { rmax[row] = m; rinv[row] = 1.f / s; }
}

// ------------------------- softmax normalize: bf16 plane (critical path) -----
__global__ void softmax_norm_bf16(const float* __restrict__ a,
                                  __nv_bfloat16* __restrict__ ph,
                                  const float* __restrict__ rmax,
                                  const float* __restrict__ rinv)
{
    const float mx = rmax[blockIdx.x];
    const float inv = rinv[blockIdx.x];
    const float4* p = (const float4*)(a + (long)blockIdx.x * G_);
    uint32_t* h32 = (uint32_t*)(ph + (long)blockIdx.x * G_);
    const int NV = G_ / 4;
    for (int i = threadIdx.x; i < NV; i += 256) {
        float4 v = p[i];
        v.x = __expf(v.x - mx) * inv;
        v.y = __expf(v.y - mx) * inv;
        v.z = __expf(v.z - mx) * inv;
        v.w = __expf(v.w - mx) * inv;
        h32[2 * i]     = pack_bf2(v.x, v.y);
        h32[2 * i + 1] = pack_bf2(v.z, v.w);
    }
}

// ------------------------- softmax normalize: fp32 in place (after ctx) ------
__global__ void softmax_norm_f32(float* __restrict__ a,
                                 const float* __restrict__ rmax,
                                 const float* __restrict__ rinv)
{
    const float mx = rmax[blockIdx.x];
    const float inv = rinv[blockIdx.x];
    float4* p = (float4*)(a + (long)blockIdx.x * G_);
    const int NV = G_ / 4;
    for (int i = threadIdx.x; i < NV; i += 256) {
        float4 v = p[i];
        v.x = __expf(v.x - mx) * inv;
        v.y = __expf(v.y - mx) * inv;
        v.z = __expf(v.z - mx) * inv;
        v.w = __expf(v.w - mx) * inv;
        p[i] = v;
    }
}

// ------------------------- fp32->bf16 hi/lo splitter -------------------------
__global__ void cvt_split(const float4* __restrict__ x,
                          __nv_bfloat162* __restrict__ hi,
                          __nv_bfloat162* __restrict__ lo, int n4)
{
    int i = blockIdx.x * blockDim.x + threadIdx.x;
    if (i >= n4) return;
    float4 v = x[i];
    float lx0, ly0, lx1, ly1;
    uint32_t h0 = pack_hi(v.x, v.y, &lx0, &ly0);
    uint32_t h1 = pack_hi(v.z, v.w, &lx1, &ly1);
    ((uint32_t*)hi)[2 * i]     = h0;
    ((uint32_t*)hi)[2 * i + 1] = h1;
    ((uint32_t*)lo)[2 * i]     = pack_bf2(lx0, ly0);
    ((uint32_t*)lo)[2 * i + 1] = pack_bf2(lx1, ly1);
}

// ------------------------- V transpose + hi/lo split -------------------------
__global__ void transpose_split(const float* __restrict__ V,
                                __nv_bfloat16* __restrict__ th,
                                __nv_bfloat16* __restrict__ tl)
{
    __shared__ float t[32][33];
    const int g0 = blockIdx.x * 32, c0 = blockIdx.y * 32;
    const int tx = threadIdx.x, ty = threadIdx.y;
#pragma unroll
    for (int j = 0; j < 4; j++) {
        int g = g0 + ty + j * 8;
        t[ty + j * 8][tx] = V[(long)g * L_ + c0 + tx];
    }
    __syncthreads();
#pragma unroll
    for (int j = 0; j < 4; j++) {
        int c = c0 + ty + j * 8;
        int g = g0 + tx;
        float x = t[tx][ty + j * 8];
        __nv_bfloat16 hi = __float2bfloat16(x);
        th[(long)c * G_ + g] = hi;
        tl[(long)c * G_ + g] = __float2bfloat16(x - __bfloat162float(hi));
    }
}

// ------------------------- split-K reduce -> planar ctx ----------------------
__global__ void reduce_ctx(const float* __restrict__ part,
                           __nv_bfloat16* __restrict__ ch,
                           __nv_bfloat16* __restrict__ cl)
{
    int idx = blockIdx.x * blockDim.x + threadIdx.x;
    if (idx >= B_ * L_) return;
    int b = idx / L_;
    int c = idx % L_;
    int h = c / HD_;
    int d = c % HD_;
    float s = 0.f;
    for (int i = 0; i < CTX_SPLITS; i++)
        s += part[(((long)h * CTX_SPLITS + i) * B_ + b) * HD_ + d];
    __nv_bfloat16 hi = __float2bfloat16(s);
    ch[idx] = hi;
    cl[idx] = __float2bfloat16(s - __bfloat162float(hi));
}

// ------------------------- LayerNorm + ReLU -> planar h ----------------------
__global__ void ln_relu(const float* __restrict__ hbuf,
                        const float* __restrict__ g, const float* __restrict__ bta,
                        __nv_bfloat16* __restrict__ hh, __nv_bfloat16* __restrict__ hl)
{
    const float* p = hbuf + (long)blockIdx.x * L_;
    __shared__ float r1[256];
    __shared__ float r2[256];
    const int t = threadIdx.x;
    float x0 = p[t], x1 = p[t + 256];
    r1[t] = x0 + x1;
    r2[t] = x0 * x0 + x1 * x1;
    __syncthreads();
    for (int s = 128; s > 0; s >>= 1) {
        if (t < s) { r1[t] += r1[t + s]; r2[t] += r2[t + s]; }
        __syncthreads();
    }
    float mu = r1[0] * (1.f / L_);
    float var = r2[0] * (1.f / L_) - mu * mu;
    float inv = rsqrtf(var + 1e-5f);
    float y0 = fmaxf((x0 - mu) * inv * g[t] + bta[t], 0.f);
    float y1 = fmaxf((x1 - mu) * inv * g[t + 256] + bta[t + 256], 0.f);
    long o = (long)blockIdx.x * L_;
    __nv_bfloat16 h0 = __float2bfloat16(y0);
    __nv_bfloat16 h1 = __float2bfloat16(y1);
    hh[o + t] = h0;
    hh[o + t + 256] = h1;
    hl[o + t] = __float2bfloat16(y0 - __bfloat162float(h0));
    hl[o + t + 256] = __float2bfloat16(y1 - __bfloat162float(h1));
}

// ------------------------- launch ---------------------------------------------
#define BF_SMEM (2 * STAGE_BYTES)

extern "C" void kernel_launch(void* const* d_in, const int* in_sizes, int n_in,
                              void* d_out, int out_size)
{
    const float* z_latent = (const float*)d_in[0];
    const float* gene_emb = (const float*)d_in[1];
    const float* Wq  = (const float*)d_in[2];
    const float* bq  = (const float*)d_in[3];
    const float* Wk  = (const float*)d_in[4];
    const float* bk  = (const float*)d_in[5];
    const float* Wv  = (const float*)d_in[6];
    const float* bv  = (const float*)d_in[7];
    const float* W1  = (const float*)d_in[8];
    const float* b1  = (const float*)d_in[9];
    const float* lng = (const float*)d_in[10];
    const float* lnb = (const float*)d_in[11];
    const float* W2  = (const float*)d_in[12];
    const float* b2  = (const float*)d_in[13];

    float* out_ga   = (float*)d_out;               // [B, G]
    float* out_attn = out_ga + (long)B_ * G_;      // [B, H, G]

    float *pV, *pCtxp, *pH, *pPmax, *pPsum, *pRmax, *pRinv;
    __nv_bfloat16 *zh, *zl, *geh, *gel, *Wqh, *Wql, *Wkh, *Wkl, *Wvh, *Wvl;
    __nv_bfloat16 *W1h, *W1l, *W2h, *W2l, *Qh, *Ql, *Kh, *Kl, *cth, *ctl, *hh, *hl;
    __nv_bfloat16 *ath, *Vth, *Vtl;
    cudaGetSymbolAddress((void**)&pV,    g_V);
    cudaGetSymbolAddress((void**)&pCtxp, g_ctxp);
    cudaGetSymbolAddress((void**)&pH,    g_h);
    cudaGetSymbolAddress((void**)&pPmax, g_pmax);
    cudaGetSymbolAddress((void**)&pPsum, g_psum);
    cudaGetSymbolAddress((void**)&pRmax, g_rmax);
    cudaGetSymbolAddress((void**)&pRinv, g_rinv);
    cudaGetSymbolAddress((void**)&zh,  g_zh);   cudaGetSymbolAddress((void**)&zl,  g_zl);
    cudaGetSymbolAddress((void**)&geh, g_geh);  cudaGetSymbolAddress((void**)&gel, g_gel);
    cudaGetSymbolAddress((void**)&Wqh, g_Wqh);  cudaGetSymbolAddress((void**)&Wql, g_Wql);
    cudaGetSymbolAddress((void**)&Wkh, g_Wkh);  cudaGetSymbolAddress((void**)&Wkl, g_Wkl);
    cudaGetSymbolAddress((void**)&Wvh, g_Wvh);  cudaGetSymbolAddress((void**)&Wvl, g_Wvl);
    cudaGetSymbolAddress((void**)&W1h, g_W1h);  cudaGetSymbolAddress((void**)&W1l, g_W1l);
    cudaGetSymbolAddress((void**)&W2h, g_W2h);  cudaGetSymbolAddress((void**)&W2l, g_W2l);
    cudaGetSymbolAddress((void**)&Qh,  g_Qh);   cudaGetSymbolAddress((void**)&Ql,  g_Ql);
    cudaGetSymbolAddress((void**)&Kh,  g_Kh);   cudaGetSymbolAddress((void**)&Kl,  g_Kl);
    cudaGetSymbolAddress((void**)&cth, g_cth);  cudaGetSymbolAddress((void**)&ctl, g_ctl);
    cudaGetSymbolAddress((void**)&hh,  g_hh);   cudaGetSymbolAddress((void**)&hl,  g_hl);
    cudaGetSymbolAddress((void**)&ath, g_ath);
    cudaGetSymbolAddress((void**)&Vth, g_Vth);  cudaGetSymbolAddress((void**)&Vtl, g_Vtl);

    cudaFuncSetAttribute(bf_gemm, cudaFuncAttributeMaxDynamicSharedMemorySize, BF_SMEM);
    cudaFuncSetAttribute(scores_gemm, cudaFuncAttributeMaxDynamicSharedMemorySize, BF_SMEM);

    static cudaStream_t sB = nullptr, sC = nullptr;
    static cudaEvent_t evGe = nullptr, evStart = nullptr, evV = nullptr, evW = nullptr;
    static cudaEvent_t evCtx = nullptr, evNF = nullptr;
    if (!sB) {
        cudaStreamCreateWithFlags(&sB, cudaStreamNonBlocking);
        cudaStreamCreateWithFlags(&sC, cudaStreamNonBlocking);
        cudaEventCreateWithFlags(&evGe,    cudaEventDisableTiming);
        cudaEventCreateWithFlags(&evStart, cudaEventDisableTiming);
        cudaEventCreateWithFlags(&evV,     cudaEventDisableTiming);
        cudaEventCreateWithFlags(&evW,     cudaEventDisableTiming);
        cudaEventCreateWithFlags(&evCtx,   cudaEventDisableTiming);
        cudaEventCreateWithFlags(&evNF,    cudaEventDisableTiming);
    }

    auto cvt = [&](const float* x, __nv_bfloat16* hi, __nv_bfloat16* lo, int n,
                   cudaStream_t st) {
        int n4 = n >> 2;
        cvt_split<<<(n4 + 255) / 256, 256, 0, st>>>(
            (const float4*)x, (__nv_bfloat162*)hi, (__nv_bfloat162*)lo, n4);
    };

    // ---- origin stream: ge convert first (V branch depends on it)
    cvt(gene_emb, geh, gel, G_ * GD_, 0);
    cudaEventRecord(evGe, 0);
    cudaEventRecord(evStart, 0);

    // ---- branch B: Wv cvt -> V proj -> transpose (joins before ctx)
    cudaStreamWaitEvent(sB, evGe, 0);
    cvt(Wv, Wvh, Wvl, L_ * GD_, sB);
    bf_gemm<<<dim3(8, 157, 1), 256, BF_SMEM, sB>>>(
        geh, gel, Wvh, Wvl, pV, bv, nullptr, nullptr,
        G_, L_, GD_, GD_, GD_, L_, 0, 0, 0, 0, 1, GD_, 1.f);
    transpose_split<<<dim3(G_ / 32, L_ / 32, 1), dim3(32, 8, 1), 0, sB>>>(pV, Vth, Vtl);
    cudaEventRecord(evV, sB);

    // ---- branch C: W1/W2 converts (join before step 8)
    cudaStreamWaitEvent(sC, evStart, 0);
    cvt(W1, W1h, W1l, L_ * L_, sC);
    cvt(W2, W2h, W2l, G_ * L_, sC);
    cudaEventRecord(evW, sC);

    // ---- origin stream: Q/K chain
    cvt(z_latent, zh, zl, B_ * L_, 0);
    cvt(Wq, Wqh, Wql, L_ * L_, 0);
    cvt(Wk, Wkh, Wkl, L_ * GD_, 0);

    bf_gemm<<<dim3(8, 2, 1), 256, BF_SMEM>>>(
        zh, zl, Wqh, Wql, nullptr, bq, Qh, Ql,
        B_, L_, L_, L_, L_, 0, L_, 0, 0, 0, 1, L_, 1.f);

    bf_gemm<<<dim3(8, 157, 1), 256, BF_SMEM>>>(
        geh, gel, Wkh, Wkl, nullptr, bk, Kh, Kl,
        G_, L_, GD_, GD_, GD_, 0, L_, 0, 0, 0, 1, GD_, 1.f);

    scores_gemm<<<dim3(NT_, 2, 1), 256, BF_SMEM>>>(Qh, Ql, Kh, Kl, out_attn,
                                                   pPmax, pPsum);

    softmax_combine<<<B_ * H_ / 8, 256>>>(pPmax, pPsum, pRmax, pRinv);

    // critical path: bf16 attn plane only (reads raw scores, no in-place write)
    softmax_norm_bf16<<<B_ * H_, 256>>>(out_attn, ath, pRmax, pRinv);

    // ---- join V branch, then ctx (attn hi-plane only: Al = nullptr)
    cudaStreamWaitEvent(0, evV, 0);
    bf_gemm<<<dim3(1, 2, H_ * CTX_SPLITS), 256, BF_SMEM>>>(
        ath, nullptr, Vth, Vtl, pCtxp, nullptr, nullptr, nullptr,
        B_, HD_, G_, H_ * G_, G_, HD_, 0,
        G_, (long)HD_ * G_, (long)B_ * HD_, CTX_SPLITS, CTX_CHUNK, 1.f);
    cudaEventRecord(evCtx, 0);

    // side stream: fp32 in-place attn finalize AFTER ctx is done (avoids
    // bandwidth contention with the ctx GEMM; overlaps reduce/W1/ln/W2).
    // evCtx also orders it after softmax_norm_bf16's read of the raw scores.
    cudaStreamWaitEvent(sC, evCtx, 0);
    softmax_norm_f32<<<B_ * H_, 256, 0, sC>>>(out_attn, pRmax, pRinv);
    cudaEventRecord(evNF, sC);

    reduce_ctx<<<(B_ * L_ + 255) / 256, 256>>>(pCtxp, cth, ctl);

    // ---- join W converts, then tail
    cudaStreamWaitEvent(0, evW, 0);
    bf_gemm<<<dim3(8, 2, 1), 256, BF_SMEM>>>(
        cth, ctl, W1h, W1l, pH, b1, nullptr, nullptr,
        B_, L_, L_, L_, L_, L_, 0, 0, 0, 0, 1, L_, 1.f);

    ln_relu<<<B_, 256>>>(pH, lng, lnb, hh, hl);

    bf_gemm<<<dim3(313, 2, 1), 256, BF_SMEM>>>(
        hh, hl, W2h, W2l, out_ga, b2, nullptr, nullptr,
        B_, G_, L_, L_, L_, G_, 0, 0, 0, 0, 1, L_, 1.f);

    // join the fp32-normalize side stream so capture sees all forks joined
    cudaStreamWaitEvent(0, evNF, 0);
}

// round 17
// speedup vs baseline: 1.1038x; 1.0948x over previous
#include <cuda_runtime.h>
#include <cuda_bf16.h>
#include <cstdint>
#include <math.h>

// Problem constants
#define B_   256
#define G_   20000
#define L_   512
#define GD_  256
#define H_   8
#define HD_  64
#define SCALE_ 0.125f
#define CTX_SPLITS 18       // 8*18*2 = 288 CTAs <= 296 concurrent -> single wave
#define CTX_CHUNK  1112     // 18*1112 >= 20000; multiple of 8 (16B-aligned k)
#define NT_  313            // score n-tiles (ceil(20000/64))

// ------------------------- device scratch (static; no allocs) ---------------
__device__ float g_V[G_ * L_];
__device__ float g_ctxp[H_ * CTX_SPLITS * B_ * HD_];
__device__ float g_h[B_ * L_];
__device__ float g_pmax[B_ * H_ * NT_];
__device__ float g_psum[B_ * H_ * NT_];
__device__ float g_rmax[B_ * H_];
__device__ float g_rinv[B_ * H_];

__device__ __nv_bfloat16 g_zh[B_ * L_],  g_zl[B_ * L_];
__device__ __nv_bfloat16 g_geh[G_ * GD_], g_gel[G_ * GD_];
__device__ __nv_bfloat16 g_Wqh[L_ * L_],  g_Wql[L_ * L_];
__device__ __nv_bfloat16 g_Wkh[L_ * GD_], g_Wkl[L_ * GD_];
__device__ __nv_bfloat16 g_Wvh[L_ * GD_], g_Wvl[L_ * GD_];
__device__ __nv_bfloat16 g_W1h[L_ * L_],  g_W1l[L_ * L_];
__device__ __nv_bfloat16 g_W2h[G_ * L_],  g_W2l[G_ * L_];
__device__ __nv_bfloat16 g_Qh[B_ * L_],  g_Ql[B_ * L_];
__device__ __nv_bfloat16 g_Kh[G_ * L_],  g_Kl[G_ * L_];
__device__ __nv_bfloat16 g_cth[B_ * L_], g_ctl[B_ * L_];
__device__ __nv_bfloat16 g_hh[B_ * L_],  g_hl[B_ * L_];
__device__ __nv_bfloat16 g_ath[B_ * H_ * G_];                        // attn hi plane
__device__ __nv_bfloat16 g_Vth[L_ * G_], g_Vtl[L_ * G_];             // V^T planes

// ------------------------- helpers ------------------------------------------
__device__ __forceinline__ uint32_t smem_u32(const void* p) {
    uint32_t addr;
    asm("{ .reg .u64 tmp; cvta.to.shared.u64 tmp, %1; cvt.u32.u64 %0, tmp; }"
        : "=r"(addr) : "l"(p));
    return addr;
}

__device__ __forceinline__ void mma16816(float* c, const uint32_t* a, const uint32_t* b)
{
    asm volatile(
        "mma.sync.aligned.m16n8k16.row.col.f32.bf16.bf16.f32 "
        "{%0,%1,%2,%3}, {%4,%5,%6,%7}, {%8,%9}, {%0,%1,%2,%3};"
        : "+f"(c[0]), "+f"(c[1]), "+f"(c[2]), "+f"(c[3])
        : "r"(a[0]), "r"(a[1]), "r"(a[2]), "r"(a[3]), "r"(b[0]), "r"(b[1]));
}

__device__ __forceinline__ void ldsm4(uint32_t* r, uint32_t addr)
{
    asm volatile("ldmatrix.sync.aligned.m8n8.x4.shared.b16 {%0,%1,%2,%3}, [%4];"
                 : "=r"(r[0]), "=r"(r[1]), "=r"(r[2]), "=r"(r[3]) : "r"(addr));
}

__device__ __forceinline__ void cpa16(uint32_t dst, const void* src, int vld)
{
    asm volatile("cp.async.cg.shared.global [%0], [%1], 16, %2;"
                 :: "r"(dst), "l"(src), "r"(vld) : "memory");
}

__device__ __forceinline__ uint32_t pack_hi(float x, float y, float* rx, float* ry)
{
    __nv_bfloat16 hx = __float2bfloat16(x);
    __nv_bfloat16 hy = __float2bfloat16(y);
    *rx = x - __bfloat162float(hx);
    *ry = y - __bfloat162float(hy);
    __nv_bfloat162 p = {hx, hy};
    return *(uint32_t*)&p;
}
__device__ __forceinline__ uint32_t pack_bf2(float x, float y)
{
    __nv_bfloat162 p = {__float2bfloat16(x), __float2bfloat16(y)};
    return *(uint32_t*)&p;
}

// ------------------------- planar bf16x3 GEMM (validated core) ---------------
// Al == nullptr -> A-hi-only mode: skips Al loads and the lo*hi MMA block.
#define STAGE_BYTES 49152

__global__ __launch_bounds__(256, 2) void bf_gemm(
    const __nv_bfloat16* __restrict__ Ah, const __nv_bfloat16* __restrict__ Al,
    const __nv_bfloat16* __restrict__ Bh, const __nv_bfloat16* __restrict__ Bl,
    float* __restrict__ C, const float* __restrict__ bias,
    __nv_bfloat16* __restrict__ Ch, __nv_bfloat16* __restrict__ Cl,
    int M, int N, int K, int lda, int ldb, long ldc, int ldcp,
    long aZ, long bZ, long cZ, int kSplit, int kChunk, float alpha)
{
    extern __shared__ char smem[];
    const uint32_t smemBase = smem_u32(smem);

    const int tid = threadIdx.x;
    const int wid = tid >> 5, lane = tid & 31;
    const int wm = wid & 3, wn = wid >> 2;

    const int z = blockIdx.z;
    const int h = z / kSplit, sK = z % kSplit;
    Ah += (long)h * aZ;
    if (Al) Al += (long)h * aZ;
    Bh += (long)h * bZ; Bl += (long)h * bZ;
    if (C) C += (long)z * cZ;
    const int kStart = sK * kChunk;
    const int kEnd = min(K, kStart + kChunk);
    const int m0 = blockIdx.y * 128, n0 = blockIdx.x * 64;

    const uint32_t x7 = lane & 7;
    const uint32_t caB = (lane >> 4) & 1;
    const uint32_t cbB = (lane >> 3) & 1;
    const uint32_t aRowOff = (uint32_t)((lane & 7) + (lane & 8));
    const uint32_t bRowOff = (uint32_t)((lane & 7) + ((lane & 16) >> 1));
    uint32_t aR[2], bR[2];
#pragma unroll
    for (int mt = 0; mt < 2; mt++) aR[mt] = (uint32_t)(wm * 32 + mt * 16 + aRowOff) * 128u;
#pragma unroll
    for (int j = 0; j < 2; j++)  bR[j] = (uint32_t)(wn * 32 + j * 16 + bRowOff) * 128u;

    float acc[2][4][4];
#pragma unroll
    for (int i = 0; i < 2; i++)
#pragma unroll
        for (int j = 0; j < 4; j++)
#pragma unroll
            for (int r = 0; r < 4; r++) acc[i][j][r] = 0.f;

    const int KI = (kEnd - kStart + 63) >> 6;

    auto load_stage = [&](int it) {
        const int k0 = kStart + (it << 6);
        const uint32_t sb = smemBase + (uint32_t)(it & 1) * STAGE_BYTES;
#pragma unroll
        for (int i = 0; i < 4; i++) {
            int e = tid + (i << 8);
            int row = e >> 3, kc = e & 7;
            int gm = m0 + row, gk = k0 + (kc << 3);
            int v = (gm < M && gk + 8 <= kEnd) ? 16 : 0;
            long off = v ? ((long)gm * lda + gk) : 0;
            uint32_t dst = sb + (uint32_t)row * 128u + ((uint32_t)(kc ^ (row & 7)) << 4);
            cpa16(dst, Ah + off, v);
            if (Al) cpa16(dst + 16384, Al + off, v);
        }
#pragma unroll
        for (int i = 0; i < 2; i++) {
            int e = tid + (i << 8);
            int row = e >> 3, kc = e & 7;
            int gn = n0 + row, gk = k0 + (kc << 3);
            int v = (gn < N && gk + 8 <= kEnd) ? 16 : 0;
            long off = v ? ((long)gn * ldb + gk) : 0;
            uint32_t dst = sb + 32768u + (uint32_t)row * 128u + ((uint32_t)(kc ^ (row & 7)) << 4);
            cpa16(dst,        Bh + off, v);
            cpa16(dst + 8192, Bl + off, v);
        }
        asm volatile("cp.async.commit_group;" ::: "memory");
    };

    load_stage(0);

    for (int it = 0; it < KI; ++it) {
        asm volatile("cp.async.wait_group 0;" ::: "memory");
        __syncthreads();
        if (it + 1 < KI) load_stage(it + 1);

        const uint32_t sb = smemBase + (uint32_t)(it & 1) * STAGE_BYTES;
        uint32_t faH[2][4], faL[2][4], fb[2][4];
#pragma unroll
        for (int s = 0; s < 4; s++) {
            const uint32_t ac = (((uint32_t)(2 * s) + caB) ^ x7) << 4;
            const uint32_t bc = (((uint32_t)(2 * s) + cbB) ^ x7) << 4;
            ldsm4(faH[0], sb + aR[0] + ac);
            ldsm4(faH[1], sb + aR[1] + ac);
            ldsm4(fb[0],  sb + 32768u + bR[0] + bc);
            ldsm4(fb[1],  sb + 32768u + bR[1] + bc);
#pragma unroll
            for (int mt = 0; mt < 2; mt++)
#pragma unroll
                for (int nt = 0; nt < 4; nt++)
                    mma16816(acc[mt][nt], faH[mt], &fb[nt >> 1][(nt & 1) << 1]);
            if (Al) {
                ldsm4(faL[0], sb + 16384u + aR[0] + ac);
                ldsm4(faL[1], sb + 16384u + aR[1] + ac);
#pragma unroll
                for (int mt = 0; mt < 2; mt++)
#pragma unroll
                    for (int nt = 0; nt < 4; nt++)
                        mma16816(acc[mt][nt], faL[mt], &fb[nt >> 1][(nt & 1) << 1]);
            }
            ldsm4(fb[0], sb + 40960u + bR[0] + bc);
            ldsm4(fb[1], sb + 40960u + bR[1] + bc);
#pragma unroll
            for (int mt = 0; mt < 2; mt++)
#pragma unroll
                for (int nt = 0; nt < 4; nt++)
                    mma16816(acc[mt][nt], faH[mt], &fb[nt >> 1][(nt & 1) << 1]);
        }
        __syncthreads();
    }

    const int grp = lane >> 2, tig = lane & 3;
#pragma unroll
    for (int mt = 0; mt < 2; mt++) {
#pragma unroll
        for (int nt = 0; nt < 4; nt++) {
            int rm = m0 + (wm << 5) + (mt << 4) + grp;
            int cn = n0 + (wn << 5) + (nt << 3) + (tig << 1);
            if (cn >= N) continue;
            float bx = 0.f, by = 0.f;
            if (bias) { bx = bias[cn]; by = bias[cn + 1]; }
#pragma unroll
            for (int rr = 0; rr < 2; rr++) {
                int r = rm + rr * 8;
                if (r >= M) continue;
                float vx = acc[mt][nt][rr * 2 + 0] * alpha + bx;
                float vy = acc[mt][nt][rr * 2 + 1] * alpha + by;
                if (C) *(float2*)&C[(long)r * ldc + cn] = make_float2(vx, vy);
                if (Ch) {
                    float lx, ly;
                    uint32_t hw = pack_hi(vx, vy, &lx, &ly);
                    uint32_t lw = pack_bf2(lx, ly);
                    *(uint32_t*)&Ch[(long)r * ldcp + cn] = hw;
                    *(uint32_t*)&Cl[(long)r * ldcp + cn] = lw;
                }
            }
        }
    }
}

// ------------------------- head-looped scores GEMM + softmax partials --------
__global__ __launch_bounds__(256, 2) void scores_gemm(
    const __nv_bfloat16* __restrict__ Ah, const __nv_bfloat16* __restrict__ Al,
    const __nv_bfloat16* __restrict__ Bh, const __nv_bfloat16* __restrict__ Bl,
    float* __restrict__ C, float* __restrict__ pmax, float* __restrict__ psum)
{
    extern __shared__ char smem[];
    __shared__ float redbuf[512];
    const uint32_t smemBase = smem_u32(smem);

    const int tid = threadIdx.x;
    const int wid = tid >> 5, lane = tid & 31;
    const int wm = wid & 3, wn = wid >> 2;
    const int m0 = blockIdx.y * 128, n0 = blockIdx.x * 64;

    const uint32_t x7 = lane & 7;
    const uint32_t caB = (lane >> 4) & 1;
    const uint32_t cbB = (lane >> 3) & 1;
    const uint32_t aRowOff = (uint32_t)((lane & 7) + (lane & 8));
    const uint32_t bRowOff = (uint32_t)((lane & 7) + ((lane & 16) >> 1));
    uint32_t aR[2], bR[2];
#pragma unroll
    for (int mt = 0; mt < 2; mt++) aR[mt] = (uint32_t)(wm * 32 + mt * 16 + aRowOff) * 128u;
#pragma unroll
    for (int j = 0; j < 2; j++)  bR[j] = (uint32_t)(wn * 32 + j * 16 + bRowOff) * 128u;

    float acc[2][4][4];
#pragma unroll
    for (int i = 0; i < 2; i++)
#pragma unroll
        for (int j = 0; j < 4; j++)
#pragma unroll
            for (int r = 0; r < 4; r++) acc[i][j][r] = 0.f;

    auto load_stage = [&](int hh) {
        const int k0 = hh << 6;
        const uint32_t sb = smemBase + (uint32_t)(hh & 1) * STAGE_BYTES;
#pragma unroll
        for (int i = 0; i < 4; i++) {
            int e = tid + (i << 8);
            int row = e >> 3, kc = e & 7;
            long off = (long)(m0 + row) * L_ + k0 + (kc << 3);
            uint32_t dst = sb + (uint32_t)row * 128u + ((uint32_t)(kc ^ (row & 7)) << 4);
            cpa16(dst,         Ah + off, 16);
            cpa16(dst + 16384, Al + off, 16);
        }
#pragma unroll
        for (int i = 0; i < 2; i++) {
            int e = tid + (i << 8);
            int row = e >> 3, kc = e & 7;
            int gn = n0 + row;
            int v = (gn < G_) ? 16 : 0;
            long off = v ? ((long)gn * L_ + k0 + (kc << 3)) : 0;
            uint32_t dst = sb + 32768u + (uint32_t)row * 128u + ((uint32_t)(kc ^ (row & 7)) << 4);
            cpa16(dst,        Bh + off, v);
            cpa16(dst + 8192, Bl + off, v);
        }
        asm volatile("cp.async.commit_group;" ::: "memory");
    };

    load_stage(0);
    const int grp = lane >> 2, tig = lane & 3;

    for (int h = 0; h < H_; ++h) {
        asm volatile("cp.async.wait_group 0;" ::: "memory");
        __syncthreads();
        if (h + 1 < H_) load_stage(h + 1);

        const uint32_t sb = smemBase + (uint32_t)(h & 1) * STAGE_BYTES;
        uint32_t faH[2][4], faL[2][4], fb[2][4];
#pragma unroll
        for (int s = 0; s < 4; s++) {
            const uint32_t ac = (((uint32_t)(2 * s) + caB) ^ x7) << 4;
            const uint32_t bc = (((uint32_t)(2 * s) + cbB) ^ x7) << 4;
            ldsm4(faH[0], sb + aR[0] + ac);
            ldsm4(faH[1], sb + aR[1] + ac);
            ldsm4(faL[0], sb + 16384u + aR[0] + ac);
            ldsm4(faL[1], sb + 16384u + aR[1] + ac);
            ldsm4(fb[0],  sb + 32768u + bR[0] + bc);
            ldsm4(fb[1],  sb + 32768u + bR[1] + bc);
#pragma unroll
            for (int mt = 0; mt < 2; mt++)
#pragma unroll
                for (int nt = 0; nt < 4; nt++)
                    mma16816(acc[mt][nt], faH[mt], &fb[nt >> 1][(nt & 1) << 1]);
#pragma unroll
            for (int mt = 0; mt < 2; mt++)
#pragma unroll
                for (int nt = 0; nt < 4; nt++)
                    mma16816(acc[mt][nt], faL[mt], &fb[nt >> 1][(nt & 1) << 1]);
            ldsm4(fb[0], sb + 40960u + bR[0] + bc);
            ldsm4(fb[1], sb + 40960u + bR[1] + bc);
#pragma unroll
            for (int mt = 0; mt < 2; mt++)
#pragma unroll
                for (int nt = 0; nt < 4; nt++)
                    mma16816(acc[mt][nt], faH[mt], &fb[nt >> 1][(nt & 1) << 1]);
        }

        // ---- per-head epilogue: write raw scores + per-(row,tile) partials
        float* Cr = C + (long)h * G_;
#pragma unroll
        for (int mt = 0; mt < 2; mt++) {
#pragma unroll
            for (int rr = 0; rr < 2; rr++) {
                int r = m0 + (wm << 5) + (mt << 4) + grp + (rr << 3);
                float vals[8];
                float mx = -1e30f;
#pragma unroll
                for (int nt = 0; nt < 4; nt++) {
                    int cn = n0 + (wn << 5) + (nt << 3) + (tig << 1);
                    float vx = acc[mt][nt][rr * 2 + 0] * SCALE_;
                    float vy = acc[mt][nt][rr * 2 + 1] * SCALE_;
                    bool ok = (cn < G_);
                    if (ok) *(float2*)&Cr[(long)r * (H_ * G_) + cn] = make_float2(vx, vy);
                    vals[nt * 2 + 0] = ok ? vx : -1e30f;
                    vals[nt * 2 + 1] = ok ? vy : -1e30f;
                    mx = fmaxf(mx, fmaxf(vals[nt * 2], vals[nt * 2 + 1]));
                }
                mx = fmaxf(mx, __shfl_xor_sync(0xffffffffu, mx, 1));
                mx = fmaxf(mx, __shfl_xor_sync(0xffffffffu, mx, 2));
                float s = 0.f;
#pragma unroll
                for (int i = 0; i < 8; i++) s += __expf(vals[i] - mx);
                s += __shfl_xor_sync(0xffffffffu, s, 1);
                s += __shfl_xor_sync(0xffffffffu, s, 2);
                if (tig == 0) {
                    int lr = (wm << 5) + (mt << 4) + (rr << 3) + grp;
                    redbuf[(wn << 7) + lr] = mx;
                    redbuf[256 + (wn << 7) + lr] = s;
                }
            }
        }
        __syncthreads();
        if (tid < 128) {
            float m0v = redbuf[tid],       m1v = redbuf[128 + tid];
            float s0v = redbuf[256 + tid], s1v = redbuf[384 + tid];
            float M = fmaxf(m0v, m1v);
            float S = s0v * __expf(m0v - M) + s1v * __expf(m1v - M);
            int b = m0 + tid;
            long prow = ((long)b * H_ + h) * NT_ + blockIdx.x;
            pmax[prow] = M;
            psum[prow] = S;
        }
#pragma unroll
        for (int mt = 0; mt < 2; mt++)
#pragma unroll
            for (int nt = 0; nt < 4; nt++)
#pragma unroll
                for (int r4 = 0; r4 < 4; r4++) acc[mt][nt][r4] = 0.f;
        __syncthreads();
    }
}

// ------------------------- softmax combine (LSE over tiles) ------------------
__global__ void softmax_combine(const float* __restrict__ pmax,
                                const float* __restrict__ psum,
                                float* __restrict__ rmax, float* __restrict__ rinv)
{
    int row = blockIdx.x * 8 + (threadIdx.x >> 5);
    int lane = threadIdx.x & 31;
    const float* pm = pmax + (long)row * NT_;
    const float* ps = psum + (long)row * NT_;
    float m = -1e30f, s = 0.f;
    for (int i = lane; i < NT_; i += 32) {
        float m2 = pm[i], s2 = ps[i];
        float M = fmaxf(m, m2);
        s = s * __expf(m - M) + s2 * __expf(m2 - M);
        m = M;
    }
#pragma unroll
    for (int off = 16; off; off >>= 1) {
        float m2 = __shfl_xor_sync(0xffffffffu, m, off);
        float s2 = __shfl_xor_sync(0xffffffffu, s, off);
        float M = fmaxf(m, m2);
        s = s * __expf(m - M) + s2 * __expf(m2 - M);
        m = M;
    }
    if (lane == 0) { rmax[row] = m; rinv[row] = 1.f / s; }
}

// ------------------------- softmax normalize (fused fp32 + bf16 plane) -------
__global__ void softmax_norm(float* __restrict__ a,
                             __nv_bfloat16* __restrict__ ph,
                             const float* __restrict__ rmax,
                             const float* __restrict__ rinv)
{
    const float mx = rmax[blockIdx.x];
    const float inv = rinv[blockIdx.x];
    float4* p = (float4*)(a + (long)blockIdx.x * G_);
    uint32_t* h32 = (uint32_t*)(ph + (long)blockIdx.x * G_);
    const int NV = G_ / 4;
    for (int i = threadIdx.x; i < NV; i += 256) {
        float4 v = p[i];
        v.x = __expf(v.x - mx) * inv;
        v.y = __expf(v.y - mx) * inv;
        v.z = __expf(v.z - mx) * inv;
        v.w = __expf(v.w - mx) * inv;
        p[i] = v;
        h32[2 * i]     = pack_bf2(v.x, v.y);
        h32[2 * i + 1] = pack_bf2(v.z, v.w);
    }
}

// ------------------------- fp32->bf16 hi/lo splitter -------------------------
__global__ void cvt_split(const float4* __restrict__ x,
                          __nv_bfloat162* __restrict__ hi,
                          __nv_bfloat162* __restrict__ lo, int n4)
{
    int i = blockIdx.x * blockDim.x + threadIdx.x;
    if (i >= n4) return;
    float4 v = x[i];
    float lx0, ly0, lx1, ly1;
    uint32_t h0 = pack_hi(v.x, v.y, &lx0, &ly0);
    uint32_t h1 = pack_hi(v.z, v.w, &lx1, &ly1);
    ((uint32_t*)hi)[2 * i]     = h0;
    ((uint32_t*)hi)[2 * i + 1] = h1;
    ((uint32_t*)lo)[2 * i]     = pack_bf2(lx0, ly0);
    ((uint32_t*)lo)[2 * i + 1] = pack_bf2(lx1, ly1);
}

// ------------------------- V transpose + hi/lo split -------------------------
__global__ void transpose_split(const float* __restrict__ V,
                                __nv_bfloat16* __restrict__ th,
                                __nv_bfloat16* __restrict__ tl)
{
    __shared__ float t[32][33];
    const int g0 = blockIdx.x * 32, c0 = blockIdx.y * 32;
    const int tx = threadIdx.x, ty = threadIdx.y;
#pragma unroll
    for (int j = 0; j < 4; j++) {
        int g = g0 + ty + j * 8;
        t[ty + j * 8][tx] = V[(long)g * L_ + c0 + tx];
    }
    __syncthreads();
#pragma unroll
    for (int j = 0; j < 4; j++) {
        int c = c0 + ty + j * 8;
        int g = g0 + tx;
        float x = t[tx][ty + j * 8];
        __nv_bfloat16 hi = __float2bfloat16(x);
        th[(long)c * G_ + g] = hi;
        tl[(long)c * G_ + g] = __float2bfloat16(x - __bfloat162float(hi));
    }
}

// ------------------------- split-K reduce -> planar ctx ----------------------
__global__ void reduce_ctx(const float* __restrict__ part,
                           __nv_bfloat16* __restrict__ ch,
                           __nv_bfloat16* __restrict__ cl)
{
    int idx = blockIdx.x * blockDim.x + threadIdx.x;
    if (idx >= B_ * L_) return;
    int b = idx / L_;
    int c = idx % L_;
    int h = c / HD_;
    int d = c % HD_;
    float s = 0.f;
    for (int i = 0; i < CTX_SPLITS; i++)
        s += part[(((long)h * CTX_SPLITS + i) * B_ + b) * HD_ + d];
    __nv_bfloat16 hi = __float2bfloat16(s);
    ch[idx] = hi;
    cl[idx] = __float2bfloat16(s - __bfloat162float(hi));
}

// ------------------------- LayerNorm + ReLU -> planar h ----------------------
__global__ void ln_relu(const float* __restrict__ hbuf,
                        const float* __restrict__ g, const float* __restrict__ bta,
                        __nv_bfloat16* __restrict__ hh, __nv_bfloat16* __restrict__ hl)
{
    const float* p = hbuf + (long)blockIdx.x * L_;
    __shared__ float r1[256];
    __shared__ float r2[256];
    const int t = threadIdx.x;
    float x0 = p[t], x1 = p[t + 256];
    r1[t] = x0 + x1;
    r2[t] = x0 * x0 + x1 * x1;
    __syncthreads();
    for (int s = 128; s > 0; s >>= 1) {
        if (t < s) { r1[t] += r1[t + s]; r2[t] += r2[t + s]; }
        __syncthreads();
    }
    float mu = r1[0] * (1.f / L_);
    float var = r2[0] * (1.f / L_) - mu * mu;
    float inv = rsqrtf(var + 1e-5f);
    float y0 = fmaxf((x0 - mu) * inv * g[t] + bta[t], 0.f);
    float y1 = fmaxf((x1 - mu) * inv * g[t + 256] + bta[t + 256], 0.f);
    long o = (long)blockIdx.x * L_;
    __nv_bfloat16 h0 = __float2bfloat16(y0);
    __nv_bfloat16 h1 = __float2bfloat16(y1);
    hh[o + t] = h0;
    hh[o + t + 256] = h1;
    hl[o + t] = __float2bfloat16(y0 - __bfloat162float(h0));
    hl[o + t + 256] = __float2bfloat16(y1 - __bfloat162float(h1));
}

// ------------------------- launch ---------------------------------------------
#define BF_SMEM (2 * STAGE_BYTES)

extern "C" void kernel_launch(void* const* d_in, const int* in_sizes, int n_in,
                              void* d_out, int out_size)
{
    const float* z_latent = (const float*)d_in[0];
    const float* gene_emb = (const float*)d_in[1];
    const float* Wq  = (const float*)d_in[2];
    const float* bq  = (const float*)d_in[3];
    const float* Wk  = (const float*)d_in[4];
    const float* bk  = (const float*)d_in[5];
    const float* Wv  = (const float*)d_in[6];
    const float* bv  = (const float*)d_in[7];
    const float* W1  = (const float*)d_in[8];
    const float* b1  = (const float*)d_in[9];
    const float* lng = (const float*)d_in[10];
    const float* lnb = (const float*)d_in[11];
    const float* W2  = (const float*)d_in[12];
    const float* b2  = (const float*)d_in[13];

    float* out_ga   = (float*)d_out;               // [B, G]
    float* out_attn = out_ga + (long)B_ * G_;      // [B, H, G]

    float *pV, *pCtxp, *pH, *pPmax, *pPsum, *pRmax, *pRinv;
    __nv_bfloat16 *zh, *zl, *geh, *gel, *Wqh, *Wql, *Wkh, *Wkl, *Wvh, *Wvl;
    __nv_bfloat16 *W1h, *W1l, *W2h, *W2l, *Qh, *Ql, *Kh, *Kl, *cth, *ctl, *hh, *hl;
    __nv_bfloat16 *ath, *Vth, *Vtl;
    cudaGetSymbolAddress((void**)&pV,    g_V);
    cudaGetSymbolAddress((void**)&pCtxp, g_ctxp);
    cudaGetSymbolAddress((void**)&pH,    g_h);
    cudaGetSymbolAddress((void**)&pPmax, g_pmax);
    cudaGetSymbolAddress((void**)&pPsum, g_psum);
    cudaGetSymbolAddress((void**)&pRmax, g_rmax);
    cudaGetSymbolAddress((void**)&pRinv, g_rinv);
    cudaGetSymbolAddress((void**)&zh,  g_zh);   cudaGetSymbolAddress((void**)&zl,  g_zl);
    cudaGetSymbolAddress((void**)&geh, g_geh);  cudaGetSymbolAddress((void**)&gel, g_gel);
    cudaGetSymbolAddress((void**)&Wqh, g_Wqh);  cudaGetSymbolAddress((void**)&Wql, g_Wql);
    cudaGetSymbolAddress((void**)&Wkh, g_Wkh);  cudaGetSymbolAddress((void**)&Wkl, g_Wkl);
    cudaGetSymbolAddress((void**)&Wvh, g_Wvh);  cudaGetSymbolAddress((void**)&Wvl, g_Wvl);
    cudaGetSymbolAddress((void**)&W1h, g_W1h);  cudaGetSymbolAddress((void**)&W1l, g_W1l);
    cudaGetSymbolAddress((void**)&W2h, g_W2h);  cudaGetSymbolAddress((void**)&W2l, g_W2l);
    cudaGetSymbolAddress((void**)&Qh,  g_Qh);   cudaGetSymbolAddress((void**)&Ql,  g_Ql);
    cudaGetSymbolAddress((void**)&Kh,  g_Kh);   cudaGetSymbolAddress((void**)&Kl,  g_Kl);
    cudaGetSymbolAddress((void**)&cth, g_cth);  cudaGetSymbolAddress((void**)&ctl, g_ctl);
    cudaGetSymbolAddress((void**)&hh,  g_hh);   cudaGetSymbolAddress((void**)&hl,  g_hl);
    cudaGetSymbolAddress((void**)&ath, g_ath);
    cudaGetSymbolAddress((void**)&Vth, g_Vth);  cudaGetSymbolAddress((void**)&Vtl, g_Vtl);

    cudaFuncSetAttribute(bf_gemm, cudaFuncAttributeMaxDynamicSharedMemorySize, BF_SMEM);
    cudaFuncSetAttribute(scores_gemm, cudaFuncAttributeMaxDynamicSharedMemorySize, BF_SMEM);

    static cudaStream_t sB = nullptr, sC = nullptr;
    static cudaEvent_t evGe = nullptr, evStart = nullptr, evV = nullptr, evW = nullptr;
    if (!sB) {
        cudaStreamCreateWithFlags(&sB, cudaStreamNonBlocking);
        cudaStreamCreateWithFlags(&sC, cudaStreamNonBlocking);
        cudaEventCreateWithFlags(&evGe,    cudaEventDisableTiming);
        cudaEventCreateWithFlags(&evStart, cudaEventDisableTiming);
        cudaEventCreateWithFlags(&evV,     cudaEventDisableTiming);
        cudaEventCreateWithFlags(&evW,     cudaEventDisableTiming);
    }

    auto cvt = [&](const float* x, __nv_bfloat16* hi, __nv_bfloat16* lo, int n,
                   cudaStream_t st) {
        int n4 = n >> 2;
        cvt_split<<<(n4 + 255) / 256, 256, 0, st>>>(
            (const float4*)x, (__nv_bfloat162*)hi, (__nv_bfloat162*)lo, n4);
    };

    // ---- origin stream: ge convert first (V branch depends on it)
    cvt(gene_emb, geh, gel, G_ * GD_, 0);
    cudaEventRecord(evGe, 0);
    cudaEventRecord(evStart, 0);

    // ---- branch B: Wv cvt -> V proj -> transpose (joins before ctx)
    cudaStreamWaitEvent(sB, evGe, 0);
    cvt(Wv, Wvh, Wvl, L_ * GD_, sB);
    bf_gemm<<<dim3(8, 157, 1), 256, BF_SMEM, sB>>>(
        geh, gel, Wvh, Wvl, pV, bv, nullptr, nullptr,
        G_, L_, GD_, GD_, GD_, L_, 0, 0, 0, 0, 1, GD_, 1.f);
    transpose_split<<<dim3(G_ / 32, L_ / 32, 1), dim3(32, 8, 1), 0, sB>>>(pV, Vth, Vtl);
    cudaEventRecord(evV, sB);

    // ---- branch C: W1/W2 converts (join before step 8)
    cudaStreamWaitEvent(sC, evStart, 0);
    cvt(W1, W1h, W1l, L_ * L_, sC);
    cvt(W2, W2h, W2l, G_ * L_, sC);
    cudaEventRecord(evW, sC);

    // ---- origin stream: Q/K chain
    cvt(z_latent, zh, zl, B_ * L_, 0);
    cvt(Wq, Wqh, Wql, L_ * L_, 0);
    cvt(Wk, Wkh, Wkl, L_ * GD_, 0);

    bf_gemm<<<dim3(8, 2, 1), 256, BF_SMEM>>>(
        zh, zl, Wqh, Wql, nullptr, bq, Qh, Ql,
        B_, L_, L_, L_, L_, 0, L_, 0, 0, 0, 1, L_, 1.f);

    bf_gemm<<<dim3(8, 157, 1), 256, BF_SMEM>>>(
        geh, gel, Wkh, Wkl, nullptr, bk, Kh, Kl,
        G_, L_, GD_, GD_, GD_, 0, L_, 0, 0, 0, 1, GD_, 1.f);

    scores_gemm<<<dim3(NT_, 2, 1), 256, BF_SMEM>>>(Qh, Ql, Kh, Kl, out_attn,
                                                   pPmax, pPsum);

    softmax_combine<<<B_ * H_ / 8, 256>>>(pPmax, pPsum, pRmax, pRinv);
    softmax_norm<<<B_ * H_, 256>>>(out_attn, ath, pRmax, pRinv);

    // ---- join V branch, then ctx (attn hi-plane only; single-wave grid)
    cudaStreamWaitEvent(0, evV, 0);
    bf_gemm<<<dim3(1, 2, H_ * CTX_SPLITS), 256, BF_SMEM>>>(
        ath, nullptr, Vth, Vtl, pCtxp, nullptr, nullptr, nullptr,
        B_, HD_, G_, H_ * G_, G_, HD_, 0,
        G_, (long)HD_ * G_, (long)B_ * HD_, CTX_SPLITS, CTX_CHUNK, 1.f);

    reduce_ctx<<<(B_ * L_ + 255) / 256, 256>>>(pCtxp, cth, ctl);

    // ---- join W converts, then tail
    cudaStreamWaitEvent(0, evW, 0);
    bf_gemm<<<dim3(8, 2, 1), 256, BF_SMEM>>>(
        cth, ctl, W1h, W1l, pH, b1, nullptr, nullptr,
        B_, L_, L_, L_, L_, L_, 0, 0, 0, 0, 1, L_, 1.f);

    ln_relu<<<B_, 256>>>(pH, lng, lnb, hh, hl);

    bf_gemm<<<dim3(313, 2, 1), 256, BF_SMEM>>>(
        hh, hl, W2h, W2l, out_ga, b2, nullptr, nullptr,
        B_, G_, L_, L_, L_, G_, 0, 0, 0, 0, 1, L_, 1.f);
}